// round 4
// baseline (speedup 1.0000x reference)
#include <cuda_runtime.h>
#include <math.h>

// HierarchicalAttention — GB300 sm_103a
//
// Inputs (metadata order):
//  0 source           (B,D)        f32   32x1024
//  1 high_level_repr  (C,B,D)      f32   65x32x1024
//  2 pos_embs         (S,B,UD)     f32   2048x32x256
//  3 low_level_repr   (S,B,D)      f32   2048x32x1024   <- 268MB, dominant
//  4 low_level_mask   (NENT,B,ENT) bool  64x32x32
//  5 high_level_mask  (1,B,C)      bool  1x32x65
//  6 W_unit           (UD,D)       f32
//  7 W_chunk          (D,D)        f32
//  8 W_out            (D,2D)       f32
//
// Output (flattened tuple, f32):
//  attn_h (B,D) | align_vectors (B,S) | ac (B,C-1) | au (B,S)

#define B_    32
#define D_    1024
#define UD_   256
#define ENT_  32
#define NENT_ 64
#define S_    2048
#define C_    65

#define OUT_ATTN 0
#define OUT_AV   (B_*D_)                 // 32768
#define OUT_AC   (OUT_AV + B_*S_)        // 98304
#define OUT_AU   (OUT_AC + B_*(C_-1))    // 100352

// ---- scratch (static device globals; no runtime allocation) ----
__device__ float g_qu[B_*UD_];
__device__ float g_qc[B_*D_];
__device__ float g_align_units[B_*S_];
__device__ float g_align_chunks[B_*C_];
__device__ float g_cpart[B_*32*D_];      // (b, s_chunk, d) partials, 4MB
__device__ float g_c[B_*D_];
__device__ int   g_mode_ll;              // 0=int32, 1=float32, 2=uint8
__device__ int   g_mode_hl;

__device__ __forceinline__ bool read_mask(const void* p, int idx, int mode) {
    if (mode == 0) return ((const int*)p)[idx] != 0;
    if (mode == 1) return ((const float*)p)[idx] != 0.0f;
    return ((const unsigned char*)p)[idx] != 0;
}

__device__ __forceinline__ float warp_sum(float v) {
    #pragma unroll
    for (int o = 16; o; o >>= 1) v += __shfl_xor_sync(0xFFFFFFFFu, v, o);
    return v;
}
__device__ __forceinline__ float warp_max(float v) {
    #pragma unroll
    for (int o = 16; o; o >>= 1) v = fmaxf(v, __shfl_xor_sync(0xFFFFFFFFu, v, o));
    return v;
}

// ---------------------------------------------------------------------------
// K0: detect the on-device encoding of the bool masks.
// Random 0/1 data makes the encodings unambiguous:
//  - int32  : every 4-byte word is exactly 0 or 1
//  - float32: every word is 0 or 0x3F800000
//  - uint8  : words are packed byte combos (>1, and never 0x3F800000)
// ---------------------------------------------------------------------------
__global__ void k_detect(const unsigned int* llm, const unsigned int* hlm) {
    __shared__ int s_ni, s_nf;
    if (threadIdx.x == 0) { s_ni = 0; s_nf = 0; }
    __syncthreads();
    const unsigned int* p = blockIdx.x ? hlm : llm;
    int n = blockIdx.x ? (B_*C_ / 4) : (NENT_*B_*ENT_ / 4);  // safe under any encoding
    int ni = 0, nf = 0;
    for (int i = threadIdx.x; i < n; i += blockDim.x) {
        unsigned int w = p[i];
        if (w > 1u) ni = 1;
        if (w != 0u && w != 0x3F800000u) nf = 1;
    }
    if (ni) atomicOr(&s_ni, 1);
    if (nf) atomicOr(&s_nf, 1);
    __syncthreads();
    if (threadIdx.x == 0) {
        int mode = (!s_ni) ? 0 : ((!s_nf) ? 1 : 2);
        if (blockIdx.x) g_mode_hl = mode; else g_mode_ll = mode;
    }
}

// ---------------------------------------------------------------------------
// K1: q_u = source @ W_unit^T (B,UD); q_c = source @ W_chunk^T (B,D).
// One warp per output element, K=1024 via float4.
// ---------------------------------------------------------------------------
__global__ void k_proj(const float* __restrict__ src,
                       const float* __restrict__ Wu,
                       const float* __restrict__ Wc) {
    int g = (blockIdx.x * blockDim.x + threadIdx.x) >> 5;
    int lane = threadIdx.x & 31;
    const float4* a;
    const float4* w;
    float* dst;
    if (g < B_*UD_) {
        int b = g >> 8, u = g & 255;
        a = (const float4*)(src) + b * (D_/4);
        w = (const float4*)(Wu)  + (size_t)u * (D_/4);
        dst = &g_qu[g];
    } else {
        int h = g - B_*UD_;
        if (h >= B_*D_) return;
        int b = h >> 10, i = h & 1023;
        a = (const float4*)(src) + b * (D_/4);
        w = (const float4*)(Wc)  + (size_t)i * (D_/4);
        dst = &g_qc[h];
    }
    float acc = 0.f;
    #pragma unroll
    for (int it = 0; it < 8; it++) {
        float4 x = a[lane + it*32], y = w[lane + it*32];
        acc += x.x*y.x + x.y*y.y + x.z*y.z + x.w*y.w;
    }
    acc = warp_sum(acc);
    if (lane == 0) *dst = acc;
}

// ---------------------------------------------------------------------------
// K2: align_units[b,s] = dot(q_u[b], pos_embs[s,b]) over UD=256.
// One warp per (s,b). SKIP masked units entirely (~50% of pe traffic).
// ---------------------------------------------------------------------------
__global__ void k_align_units(const float* __restrict__ pe, const void* llm) {
    int g = (blockIdx.x * 256 + threadIdx.x) >> 5;   // 0..65535
    int lane = threadIdx.x & 31;
    int b = g & 31, s = g >> 5;
    int e = s >> 5, k = s & 31;
    if (read_mask(llm, e * (B_*ENT_) + b * ENT_ + k, g_mode_ll)) return;
    const float4* p = (const float4*)(pe) + ((size_t)s * B_ + b) * (UD_/4);
    const float4* q = (const float4*)(g_qu) + b * (UD_/4);
    float acc = 0.f;
    #pragma unroll
    for (int it = 0; it < 2; it++) {
        float4 x = p[lane + it*32], y = q[lane + it*32];
        acc += x.x*y.x + x.y*y.y + x.z*y.z + x.w*y.w;
    }
    acc = warp_sum(acc);
    if (lane == 0) g_align_units[b * S_ + s] = acc;
}

// ---------------------------------------------------------------------------
// K3: align_chunks[b,c] = dot(q_c[b], hl[c,b]) over D=1024.
// One warp per (c,b). Skip masked chunks (value replaced by -inf anyway).
// ---------------------------------------------------------------------------
__global__ void k_align_chunks(const float* __restrict__ hl, const void* hlm) {
    int g = (blockIdx.x * 256 + threadIdx.x) >> 5;   // 0..2079
    int lane = threadIdx.x & 31;
    int b = g & 31, c = g >> 5;
    if (c >= C_) return;
    if (c > 0 && read_mask(hlm, b * C_ + c, g_mode_hl)) return;
    const float4* p = (const float4*)(hl) + ((size_t)c * B_ + b) * (D_/4);
    const float4* q = (const float4*)(g_qc) + b * (D_/4);
    float acc = 0.f;
    #pragma unroll
    for (int it = 0; it < 8; it++) {
        float4 x = p[lane + it*32], y = q[lane + it*32];
        acc += x.x*y.x + x.y*y.y + x.z*y.z + x.w*y.w;
    }
    acc = warp_sum(acc);
    if (lane == 0) g_align_chunks[b * C_ + c] = acc;
}

// ---------------------------------------------------------------------------
// K4: fused masked softmaxes + align_vectors. One block per batch row.
// Writes av, ac, au sections of d_out.
// ---------------------------------------------------------------------------
__global__ void k_softmax(const void* llm, const void* hlm, float* __restrict__ out) {
    int b = blockIdx.x, t = threadIdx.x;
    __shared__ float s_raw[C_];
    __shared__ float s_acs[C_-1];

    int mhl = g_mode_hl, mll = g_mode_ll;
    if (t < C_) {
        float v = g_align_chunks[b * C_ + t];
        if (read_mask(hlm, b * C_ + t, mhl)) v = -INFINITY;
        s_raw[t] = v;
    }
    __syncthreads();
    if (t == 0) {
        float mx = -INFINITY;
        for (int c = 0; c < C_; c++) mx = fmaxf(mx, s_raw[c]);
        float sum = 0.f;
        for (int c = 0; c < C_; c++) {
            float e = (s_raw[c] == -INFINITY) ? 0.f : __expf(s_raw[c] - mx);
            s_raw[c] = e; sum += e;
        }
        float inv = 1.f / sum;
        for (int c = 1; c < C_; c++) {
            float v = s_raw[c] * inv;
            s_acs[c-1] = v;
            out[OUT_AC + b * (C_-1) + (c-1)] = v;
        }
    }
    __syncthreads();

    int w = t >> 5, k = t & 31;
    for (int e = w; e < NENT_; e += 8) {
        float v = g_align_units[b * S_ + e * ENT_ + k];
        if (read_mask(llm, e * (B_*ENT_) + b * ENT_ + k, mll)) v = -INFINITY;
        float mx = warp_max(v);
        float au;
        if (mx == -INFINITY) {
            au = 0.f;                          // all-masked entity -> zeros
        } else {
            float ex = (v == -INFINITY) ? 0.f : __expf(v - mx);
            float sm = warp_sum(ex);
            au = ex / sm;
        }
        float av = au * s_acs[e];
        int s = e * ENT_ + k;
        out[OUT_AU + b * S_ + s] = au;
        out[OUT_AV + b * S_ + s] = av;
    }
}

// ---------------------------------------------------------------------------
// K5: c_partial[b,sc,:] = sum_{s in chunk sc} av[b,s] * ll[s,b,:].
// Block = (sc, b), 256 threads x float4 cover D=1024.
// KEY: av[b,s] == 0 exactly for ~75% of rows -> skip the 4KB load (uniform
// branch per block). Nominal 268MB -> ~67MB effective DRAM traffic.
// ---------------------------------------------------------------------------
__global__ void k_context(const float* __restrict__ ll, const float* __restrict__ out) {
    int sc = blockIdx.x, b = blockIdx.y, t = threadIdx.x;
    __shared__ float sw[64];
    if (t < 64) sw[t] = out[OUT_AV + b * S_ + sc * 64 + t];
    __syncthreads();
    float4 acc = make_float4(0.f, 0.f, 0.f, 0.f);
    const float4* base = (const float4*)ll;
    #pragma unroll 4
    for (int j = 0; j < 64; j++) {
        float w = sw[j];
        if (w != 0.f) {
            size_t s = (size_t)(sc * 64 + j);
            float4 v = base[s * (B_ * D_ / 4) + b * (D_/4) + t];
            acc.x += w * v.x; acc.y += w * v.y;
            acc.z += w * v.z; acc.w += w * v.w;
        }
    }
    ((float4*)g_cpart)[((b * 32 + sc) * D_ + t * 4) >> 2] = acc;
}

// ---------------------------------------------------------------------------
// K6: c[b,d] = sum_sc c_partial[b,sc,d]
// ---------------------------------------------------------------------------
__global__ void k_reduce() {
    int idx = blockIdx.x * 256 + threadIdx.x;   // 32768 total
    int b = idx >> 10, d = idx & 1023;
    float s = 0.f;
    #pragma unroll
    for (int sc = 0; sc < 32; sc++) s += g_cpart[((b << 5) + sc) * D_ + d];
    g_c[idx] = s;
}

// ---------------------------------------------------------------------------
// K7: attn_h = tanh(concat(c, source) @ W_out^T).
// Tiled GEMM: 128 blocks, each owns an 8-wide N tile -> W_out (8MB) is read
// from DRAM exactly once (vs 32x = 256MB with warp-per-output).
// Block tile: M=32 (all batch rows) x N=8, K-tiles of 64.
// ---------------------------------------------------------------------------
__global__ void k_gemm(const float* __restrict__ src,
                       const float* __restrict__ Wo,
                       float* __restrict__ out) {
    __shared__ __align__(16) float As[32][68];
    __shared__ __align__(16) float Bs[8][68];
    int t = threadIdx.x;
    int n0 = blockIdx.x * 8;
    int m = t & 31, nl = t >> 5;
    float acc = 0.f;
    for (int kt = 0; kt < 32; kt++) {
        int k0 = kt * 64;
        const float* Asrc = (kt < 16) ? g_c : src;
        int kb = (kt < 16) ? k0 : (k0 - D_);
        #pragma unroll
        for (int i = 0; i < 8; i++) {
            int idx = t + i * 256;
            int r = idx >> 6, c = idx & 63;
            As[r][c] = Asrc[r * D_ + kb + c];
        }
        #pragma unroll
        for (int i = 0; i < 2; i++) {
            int idx = t + i * 256;
            int r = idx >> 6, c = idx & 63;
            Bs[r][c] = Wo[(size_t)(n0 + r) * (2*D_) + k0 + c];
        }
        __syncthreads();
        #pragma unroll
        for (int kk = 0; kk < 64; kk += 4) {
            float4 a  = *(const float4*)&As[m][kk];
            float4 bv = *(const float4*)&Bs[nl][kk];
            acc += a.x*bv.x + a.y*bv.y + a.z*bv.z + a.w*bv.w;
        }
        __syncthreads();
    }
    out[OUT_ATTN + m * D_ + n0 + nl] = tanhf(acc);
}

// ---------------------------------------------------------------------------
extern "C" void kernel_launch(void* const* d_in, const int* in_sizes, int n_in,
                              void* d_out, int out_size) {
    const float* src = (const float*)d_in[0];
    const float* hl  = (const float*)d_in[1];
    const float* pe  = (const float*)d_in[2];
    const float* ll  = (const float*)d_in[3];
    const void*  llm = d_in[4];
    const void*  hlm = d_in[5];
    const float* Wu  = (const float*)d_in[6];
    const float* Wc  = (const float*)d_in[7];
    const float* Wo  = (const float*)d_in[8];
    float* out = (float*)d_out;

    k_detect<<<2, 256>>>((const unsigned int*)llm, (const unsigned int*)hlm);
    k_proj<<<(B_*UD_ + B_*D_) / 8, 256>>>(src, Wu, Wc);          // 5120 blocks
    k_align_units<<<(B_*S_) / 8, 256>>>(pe, llm);                // 8192 blocks
    k_align_chunks<<<(B_*C_ + 7) / 8, 256>>>(hl, hlm);           // 260 blocks
    k_softmax<<<B_, 256>>>(llm, hlm, out);
    k_context<<<dim3(32, B_), 256>>>(ll, out);
    k_reduce<<<B_*D_ / 256, 256>>>();
    k_gemm<<<D_ / 8, 256>>>(src, Wo, out);
}

// round 6
// speedup vs baseline: 1.0024x; 1.0024x over previous
#include <cuda_runtime.h>
#include <math.h>

// HierarchicalAttention — GB300 sm_103a
//
// Inputs (metadata order):
//  0 source           (B,D)        f32   32x1024
//  1 high_level_repr  (C,B,D)      f32   65x32x1024
//  2 pos_embs         (S,B,UD)     f32   2048x32x256
//  3 low_level_repr   (S,B,D)      f32   2048x32x1024   <- 268MB, dominant
//  4 low_level_mask   (NENT,B,ENT) bool  64x32x32
//  5 high_level_mask  (1,B,C)      bool  1x32x65
//  6 W_unit           (UD,D)       f32
//  7 W_chunk          (D,D)        f32
//  8 W_out            (D,2D)       f32
//
// Output (flattened tuple, f32):
//  attn_h (B,D) | align_vectors (B,S) | ac (B,C-1) | au (B,S)

#define B_    32
#define D_    1024
#define UD_   256
#define ENT_  32
#define NENT_ 64
#define S_    2048
#define C_    65

#define OUT_ATTN 0
#define OUT_AV   (B_*D_)                 // 32768
#define OUT_AC   (OUT_AV + B_*S_)        // 98304
#define OUT_AU   (OUT_AC + B_*(C_-1))    // 100352

// ---- scratch (static device globals; no runtime allocation) ----
__device__ float g_qu[B_*UD_];
__device__ float g_qc[B_*D_];
__device__ float g_align_units[B_*S_];
__device__ float g_align_chunks[B_*C_];
__device__ float g_cpart[B_*32*D_];      // (b, s_chunk, d) partials, 4MB
__device__ float g_c[B_*D_];
__device__ int   g_mode_ll;              // 0=int32, 1=float32, 2=uint8
__device__ int   g_mode_hl;

__device__ __forceinline__ bool read_mask(const void* p, int idx, int mode) {
    if (mode == 0) return ((const int*)p)[idx] != 0;
    if (mode == 1) return ((const float*)p)[idx] != 0.0f;
    return ((const unsigned char*)p)[idx] != 0;
}

__device__ __forceinline__ float warp_sum(float v) {
    #pragma unroll
    for (int o = 16; o; o >>= 1) v += __shfl_xor_sync(0xFFFFFFFFu, v, o);
    return v;
}
__device__ __forceinline__ float warp_max(float v) {
    #pragma unroll
    for (int o = 16; o; o >>= 1) v = fmaxf(v, __shfl_xor_sync(0xFFFFFFFFu, v, o));
    return v;
}

// ---------------------------------------------------------------------------
// K0: detect the on-device encoding of the bool masks.
// Random 0/1 data makes the encodings unambiguous:
//  - int32  : every 4-byte word is exactly 0 or 1
//  - float32: every word is 0 or 0x3F800000
//  - uint8  : words are packed byte combos (>1, and never 0x3F800000)
// ---------------------------------------------------------------------------
__global__ void k_detect(const unsigned int* llm, const unsigned int* hlm) {
    __shared__ int s_ni, s_nf;
    if (threadIdx.x == 0) { s_ni = 0; s_nf = 0; }
    __syncthreads();
    const unsigned int* p = blockIdx.x ? hlm : llm;
    int n = blockIdx.x ? (B_*C_ / 4) : (NENT_*B_*ENT_ / 4);  // safe under any encoding
    int ni = 0, nf = 0;
    for (int i = threadIdx.x; i < n; i += blockDim.x) {
        unsigned int w = p[i];
        if (w > 1u) ni = 1;
        if (w != 0u && w != 0x3F800000u) nf = 1;
    }
    if (ni) atomicOr(&s_ni, 1);
    if (nf) atomicOr(&s_nf, 1);
    __syncthreads();
    if (threadIdx.x == 0) {
        int mode = (!s_ni) ? 0 : ((!s_nf) ? 1 : 2);
        if (blockIdx.x) g_mode_hl = mode; else g_mode_ll = mode;
    }
}

// ---------------------------------------------------------------------------
// K1: q_u = source @ W_unit^T (B,UD); q_c = source @ W_chunk^T (B,D).
// One warp per output element, K=1024 via float4.
// ---------------------------------------------------------------------------
__global__ void k_proj(const float* __restrict__ src,
                       const float* __restrict__ Wu,
                       const float* __restrict__ Wc) {
    int g = (blockIdx.x * blockDim.x + threadIdx.x) >> 5;
    int lane = threadIdx.x & 31;
    const float4* a;
    const float4* w;
    float* dst;
    if (g < B_*UD_) {
        int b = g >> 8, u = g & 255;
        a = (const float4*)(src) + b * (D_/4);
        w = (const float4*)(Wu)  + (size_t)u * (D_/4);
        dst = &g_qu[g];
    } else {
        int h = g - B_*UD_;
        if (h >= B_*D_) return;
        int b = h >> 10, i = h & 1023;
        a = (const float4*)(src) + b * (D_/4);
        w = (const float4*)(Wc)  + (size_t)i * (D_/4);
        dst = &g_qc[h];
    }
    float acc = 0.f;
    #pragma unroll
    for (int it = 0; it < 8; it++) {
        float4 x = a[lane + it*32], y = w[lane + it*32];
        acc += x.x*y.x + x.y*y.y + x.z*y.z + x.w*y.w;
    }
    acc = warp_sum(acc);
    if (lane == 0) *dst = acc;
}

// ---------------------------------------------------------------------------
// K2: align_units[b,s] = dot(q_u[b], pos_embs[s,b]) over UD=256.
// One warp per (s,b). SKIP masked units entirely (~50% of pe traffic).
// ---------------------------------------------------------------------------
__global__ void k_align_units(const float* __restrict__ pe, const void* llm) {
    int g = (blockIdx.x * 256 + threadIdx.x) >> 5;   // 0..65535
    int lane = threadIdx.x & 31;
    int b = g & 31, s = g >> 5;
    int e = s >> 5, k = s & 31;
    if (read_mask(llm, e * (B_*ENT_) + b * ENT_ + k, g_mode_ll)) return;
    const float4* p = (const float4*)(pe) + ((size_t)s * B_ + b) * (UD_/4);
    const float4* q = (const float4*)(g_qu) + b * (UD_/4);
    float acc = 0.f;
    #pragma unroll
    for (int it = 0; it < 2; it++) {
        float4 x = p[lane + it*32], y = q[lane + it*32];
        acc += x.x*y.x + x.y*y.y + x.z*y.z + x.w*y.w;
    }
    acc = warp_sum(acc);
    if (lane == 0) g_align_units[b * S_ + s] = acc;
}

// ---------------------------------------------------------------------------
// K3: align_chunks[b,c] = dot(q_c[b], hl[c,b]) over D=1024.
// One warp per (c,b). Skip masked chunks (value replaced by -inf anyway).
// ---------------------------------------------------------------------------
__global__ void k_align_chunks(const float* __restrict__ hl, const void* hlm) {
    int g = (blockIdx.x * 256 + threadIdx.x) >> 5;   // 0..2079
    int lane = threadIdx.x & 31;
    int b = g & 31, c = g >> 5;
    if (c >= C_) return;
    if (c > 0 && read_mask(hlm, b * C_ + c, g_mode_hl)) return;
    const float4* p = (const float4*)(hl) + ((size_t)c * B_ + b) * (D_/4);
    const float4* q = (const float4*)(g_qc) + b * (D_/4);
    float acc = 0.f;
    #pragma unroll
    for (int it = 0; it < 8; it++) {
        float4 x = p[lane + it*32], y = q[lane + it*32];
        acc += x.x*y.x + x.y*y.y + x.z*y.z + x.w*y.w;
    }
    acc = warp_sum(acc);
    if (lane == 0) g_align_chunks[b * C_ + c] = acc;
}

// ---------------------------------------------------------------------------
// K4: fused masked softmaxes + align_vectors. One block per batch row.
// Writes av, ac, au sections of d_out.
// ---------------------------------------------------------------------------
__global__ void k_softmax(const void* llm, const void* hlm, float* __restrict__ out) {
    int b = blockIdx.x, t = threadIdx.x;
    __shared__ float s_raw[C_];
    __shared__ float s_acs[C_-1];

    int mhl = g_mode_hl, mll = g_mode_ll;
    if (t < C_) {
        float v = g_align_chunks[b * C_ + t];
        if (read_mask(hlm, b * C_ + t, mhl)) v = -INFINITY;
        s_raw[t] = v;
    }
    __syncthreads();
    if (t == 0) {
        float mx = -INFINITY;
        for (int c = 0; c < C_; c++) mx = fmaxf(mx, s_raw[c]);
        float sum = 0.f;
        for (int c = 0; c < C_; c++) {
            float e = (s_raw[c] == -INFINITY) ? 0.f : __expf(s_raw[c] - mx);
            s_raw[c] = e; sum += e;
        }
        float inv = 1.f / sum;
        for (int c = 1; c < C_; c++) {
            float v = s_raw[c] * inv;
            s_acs[c-1] = v;
            out[OUT_AC + b * (C_-1) + (c-1)] = v;
        }
    }
    __syncthreads();

    int w = t >> 5, k = t & 31;
    for (int e = w; e < NENT_; e += 8) {
        float v = g_align_units[b * S_ + e * ENT_ + k];
        if (read_mask(llm, e * (B_*ENT_) + b * ENT_ + k, mll)) v = -INFINITY;
        float mx = warp_max(v);
        float au;
        if (mx == -INFINITY) {
            au = 0.f;                          // all-masked entity -> zeros
        } else {
            float ex = (v == -INFINITY) ? 0.f : __expf(v - mx);
            float sm = warp_sum(ex);
            au = ex / sm;
        }
        float av = au * s_acs[e];
        int s = e * ENT_ + k;
        out[OUT_AU + b * S_ + s] = au;
        out[OUT_AV + b * S_ + s] = av;
    }
}

// ---------------------------------------------------------------------------
// K5: c_partial[b,sc,:] = sum_{s in chunk sc} av[b,s] * ll[s,b,:].
// Block = (sc, b), 256 threads x float4 cover D=1024.
// KEY: av[b,s] == 0 exactly for ~75% of rows -> skip the 4KB load (uniform
// branch per block). Nominal 268MB -> ~67MB effective DRAM traffic.
// ---------------------------------------------------------------------------
__global__ void k_context(const float* __restrict__ ll, const float* __restrict__ out) {
    int sc = blockIdx.x, b = blockIdx.y, t = threadIdx.x;
    __shared__ float sw[64];
    if (t < 64) sw[t] = out[OUT_AV + b * S_ + sc * 64 + t];
    __syncthreads();
    float4 acc = make_float4(0.f, 0.f, 0.f, 0.f);
    const float4* base = (const float4*)ll;
    #pragma unroll 4
    for (int j = 0; j < 64; j++) {
        float w = sw[j];
        if (w != 0.f) {
            size_t s = (size_t)(sc * 64 + j);
            float4 v = base[s * (B_ * D_ / 4) + b * (D_/4) + t];
            acc.x += w * v.x; acc.y += w * v.y;
            acc.z += w * v.z; acc.w += w * v.w;
        }
    }
    ((float4*)g_cpart)[((b * 32 + sc) * D_ + t * 4) >> 2] = acc;
}

// ---------------------------------------------------------------------------
// K6: c[b,d] = sum_sc c_partial[b,sc,d]
// ---------------------------------------------------------------------------
__global__ void k_reduce() {
    int idx = blockIdx.x * 256 + threadIdx.x;   // 32768 total
    int b = idx >> 10, d = idx & 1023;
    float s = 0.f;
    #pragma unroll
    for (int sc = 0; sc < 32; sc++) s += g_cpart[((b << 5) + sc) * D_ + d];
    g_c[idx] = s;
}

// ---------------------------------------------------------------------------
// K7: attn_h = tanh(concat(c, source) @ W_out^T).
// Tiled GEMM: 128 blocks, each owns an 8-wide N tile -> W_out (8MB) is read
// from DRAM exactly once (vs 32x = 256MB with warp-per-output).
// Block tile: M=32 (all batch rows) x N=8, K-tiles of 64.
// ---------------------------------------------------------------------------
__global__ void k_gemm(const float* __restrict__ src,
                       const float* __restrict__ Wo,
                       float* __restrict__ out) {
    __shared__ __align__(16) float As[32][68];
    __shared__ __align__(16) float Bs[8][68];
    int t = threadIdx.x;
    int n0 = blockIdx.x * 8;
    int m = t & 31, nl = t >> 5;
    float acc = 0.f;
    for (int kt = 0; kt < 32; kt++) {
        int k0 = kt * 64;
        const float* Asrc = (kt < 16) ? g_c : src;
        int kb = (kt < 16) ? k0 : (k0 - D_);
        #pragma unroll
        for (int i = 0; i < 8; i++) {
            int idx = t + i * 256;
            int r = idx >> 6, c = idx & 63;
            As[r][c] = Asrc[r * D_ + kb + c];
        }
        #pragma unroll
        for (int i = 0; i < 2; i++) {
            int idx = t + i * 256;
            int r = idx >> 6, c = idx & 63;
            Bs[r][c] = Wo[(size_t)(n0 + r) * (2*D_) + k0 + c];
        }
        __syncthreads();
        #pragma unroll
        for (int kk = 0; kk < 64; kk += 4) {
            float4 a  = *(const float4*)&As[m][kk];
            float4 bv = *(const float4*)&Bs[nl][kk];
            acc += a.x*bv.x + a.y*bv.y + a.z*bv.z + a.w*bv.w;
        }
        __syncthreads();
    }
    out[OUT_ATTN + m * D_ + n0 + nl] = tanhf(acc);
}

// ---------------------------------------------------------------------------
extern "C" void kernel_launch(void* const* d_in, const int* in_sizes, int n_in,
                              void* d_out, int out_size) {
    const float* src = (const float*)d_in[0];
    const float* hl  = (const float*)d_in[1];
    const float* pe  = (const float*)d_in[2];
    const float* ll  = (const float*)d_in[3];
    const void*  llm = d_in[4];
    const void*  hlm = d_in[5];
    const float* Wu  = (const float*)d_in[6];
    const float* Wc  = (const float*)d_in[7];
    const float* Wo  = (const float*)d_in[8];
    float* out = (float*)d_out;

    k_detect<<<2, 256>>>((const unsigned int*)llm, (const unsigned int*)hlm);
    k_proj<<<(B_*UD_ + B_*D_) / 8, 256>>>(src, Wu, Wc);          // 5120 blocks
    k_align_units<<<(B_*S_) / 8, 256>>>(pe, llm);                // 8192 blocks
    k_align_chunks<<<(B_*C_ + 7) / 8, 256>>>(hl, hlm);           // 260 blocks
    k_softmax<<<B_, 256>>>(llm, hlm, out);
    k_context<<<dim3(32, B_), 256>>>(ll, out);
    k_reduce<<<B_*D_ / 256, 256>>>();
    k_gemm<<<D_ / 8, 256>>>(src, Wo, out);
}

// round 9
// speedup vs baseline: 1.2125x; 1.2096x over previous
#include <cuda_runtime.h>
#include <math.h>

// HierarchicalAttention — GB300 sm_103a, R7
//
//  0 source           (B,D)        f32   32x1024
//  1 high_level_repr  (C,B,D)      f32   65x32x1024
//  2 pos_embs         (S,B,UD)     f32   2048x32x256
//  3 low_level_repr   (S,B,D)      f32   2048x32x1024   <- 268MB, dominant
//  4 low_level_mask   (NENT,B,ENT) bool
//  5 high_level_mask  (1,B,C)      bool
//  6 W_unit (UD,D) | 7 W_chunk (D,D) | 8 W_out (D,2D)
//
// Output: attn_h (B,D) | align_vectors (B,S) | ac (B,C-1) | au (B,S)

#define B_    32
#define D_    1024
#define UD_   256
#define ENT_  32
#define NENT_ 64
#define S_    2048
#define C_    65

#define OUT_ATTN 0
#define OUT_AV   (B_*D_)
#define OUT_AC   (OUT_AV + B_*S_)
#define OUT_AU   (OUT_AC + B_*(C_-1))

// ---- static scratch ----
__device__ float g_qu[B_*UD_];
__device__ float g_qc[B_*D_];
__device__ float g_align_units[B_*S_];
__device__ float g_align_chunks[B_*C_];
__device__ float g_cpart[B_*NENT_*D_];   // (b, e, d) partials, 8MB
__device__ float g_c[B_*D_];
__device__ int   g_mode_ll;              // 0=int32, 1=float32, 2=uint8
__device__ int   g_mode_hl;

__device__ __forceinline__ bool read_mask(const void* p, int idx, int mode) {
    if (mode == 0) return ((const int*)p)[idx] != 0;
    if (mode == 1) return ((const float*)p)[idx] != 0.0f;
    return ((const unsigned char*)p)[idx] != 0;
}
__device__ __forceinline__ float warp_sum(float v) {
    #pragma unroll
    for (int o = 16; o; o >>= 1) v += __shfl_xor_sync(0xFFFFFFFFu, v, o);
    return v;
}
__device__ __forceinline__ float warp_max(float v) {
    #pragma unroll
    for (int o = 16; o; o >>= 1) v = fmaxf(v, __shfl_xor_sync(0xFFFFFFFFu, v, o));
    return v;
}

// ---------------------------------------------------------------------------
// K1: projections (blocks 0..5119) + mask-dtype detection (blocks 5120,5121).
// ---------------------------------------------------------------------------
__global__ void k_front(const float* __restrict__ src,
                        const float* __restrict__ Wu,
                        const float* __restrict__ Wc,
                        const unsigned int* __restrict__ llm,
                        const unsigned int* __restrict__ hlm) {
    if (blockIdx.x >= 5120) {
        // mask encoding detection: int32 words are {0,1}; f32 words are
        // {0, 0x3F800000}; packed uint8 words hit neither set.
        __shared__ int s_ni, s_nf;
        if (threadIdx.x == 0) { s_ni = 0; s_nf = 0; }
        __syncthreads();
        int which = blockIdx.x - 5120;
        const unsigned int* p = which ? hlm : llm;
        int n = which ? (B_*C_ / 4) : (NENT_*B_*ENT_ / 4);
        int ni = 0, nf = 0;
        for (int i = threadIdx.x; i < n; i += blockDim.x) {
            unsigned int w = p[i];
            if (w > 1u) ni = 1;
            if (w != 0u && w != 0x3F800000u) nf = 1;
        }
        if (ni) atomicOr(&s_ni, 1);
        if (nf) atomicOr(&s_nf, 1);
        __syncthreads();
        if (threadIdx.x == 0) {
            int mode = (!s_ni) ? 0 : ((!s_nf) ? 1 : 2);
            if (which) g_mode_hl = mode; else g_mode_ll = mode;
        }
        return;
    }
    int g = (blockIdx.x * blockDim.x + threadIdx.x) >> 5;
    int lane = threadIdx.x & 31;
    const float4 *a, *w;
    float* dst;
    if (g < B_*UD_) {
        int b = g >> 8, u = g & 255;
        a = (const float4*)(src) + b * (D_/4);
        w = (const float4*)(Wu)  + (size_t)u * (D_/4);
        dst = &g_qu[g];
    } else {
        int h = g - B_*UD_;
        int b = h >> 10, i = h & 1023;
        a = (const float4*)(src) + b * (D_/4);
        w = (const float4*)(Wc)  + (size_t)i * (D_/4);
        dst = &g_qc[h];
    }
    float acc = 0.f;
    #pragma unroll
    for (int it = 0; it < 8; it++) {
        float4 x = a[lane + it*32], y = w[lane + it*32];
        acc += x.x*y.x + x.y*y.y + x.z*y.z + x.w*y.w;
    }
    acc = warp_sum(acc);
    if (lane == 0) *dst = acc;
}

// ---------------------------------------------------------------------------
// K2: fused unit + chunk alignment dots. Masked rows skipped (no load).
//   blocks [0, 8192): units — warp per (s,b), UD=256 dot
//   blocks [8192, 8452): chunks — warp per (c,b), D=1024 dot
// ---------------------------------------------------------------------------
__global__ void k_align(const float* __restrict__ pe,
                        const float* __restrict__ hl,
                        const void* llm, const void* hlm) {
    int lane = threadIdx.x & 31;
    if (blockIdx.x < 8192) {
        int g = (blockIdx.x * 256 + threadIdx.x) >> 5;   // (s,b) pair id
        int b = g & 31, s = g >> 5;
        int e = s >> 5, k = s & 31;
        if (read_mask(llm, e * (B_*ENT_) + b * ENT_ + k, g_mode_ll)) return;
        const float4* p = (const float4*)(pe) + ((size_t)s * B_ + b) * (UD_/4);
        const float4* q = (const float4*)(g_qu) + b * (UD_/4);
        float acc = 0.f;
        #pragma unroll
        for (int it = 0; it < 2; it++) {
            float4 x = p[lane + it*32], y = q[lane + it*32];
            acc += x.x*y.x + x.y*y.y + x.z*y.z + x.w*y.w;
        }
        acc = warp_sum(acc);
        if (lane == 0) g_align_units[b * S_ + s] = acc;
    } else {
        int g = ((blockIdx.x - 8192) * 256 + threadIdx.x) >> 5;
        int b = g & 31, c = g >> 5;
        if (c >= C_) return;
        if (c > 0 && read_mask(hlm, b * C_ + c, g_mode_hl)) return;
        const float4* p = (const float4*)(hl) + ((size_t)c * B_ + b) * (D_/4);
        const float4* q = (const float4*)(g_qc) + b * (D_/4);
        float acc = 0.f;
        #pragma unroll
        for (int it = 0; it < 8; it++) {
            float4 x = p[lane + it*32], y = q[lane + it*32];
            acc += x.x*y.x + x.y*y.y + x.z*y.z + x.w*y.w;
        }
        acc = warp_sum(acc);
        if (lane == 0) g_align_chunks[b * C_ + c] = acc;
    }
}

// ---------------------------------------------------------------------------
// K3: fused masked softmaxes + align_vectors. One block per batch row.
// ---------------------------------------------------------------------------
__global__ void k_softmax(const void* llm, const void* hlm, float* __restrict__ out) {
    int b = blockIdx.x, t = threadIdx.x;
    __shared__ float s_raw[C_];
    __shared__ float s_acs[C_-1];

    int mhl = g_mode_hl, mll = g_mode_ll;
    if (t < C_) {
        float v = g_align_chunks[b * C_ + t];
        if (read_mask(hlm, b * C_ + t, mhl)) v = -INFINITY;
        s_raw[t] = v;
    }
    __syncthreads();
    if (t == 0) {
        float mx = -INFINITY;
        for (int c = 0; c < C_; c++) mx = fmaxf(mx, s_raw[c]);
        float sum = 0.f;
        for (int c = 0; c < C_; c++) {
            float e = (s_raw[c] == -INFINITY) ? 0.f : __expf(s_raw[c] - mx);
            s_raw[c] = e; sum += e;
        }
        float inv = 1.f / sum;
        for (int c = 1; c < C_; c++) {
            float v = s_raw[c] * inv;
            s_acs[c-1] = v;
            out[OUT_AC + b * (C_-1) + (c-1)] = v;
        }
    }
    __syncthreads();

    int w = t >> 5, k = t & 31;
    for (int e = w; e < NENT_; e += 8) {
        float v = g_align_units[b * S_ + e * ENT_ + k];
        if (read_mask(llm, e * (B_*ENT_) + b * ENT_ + k, mll)) v = -INFINITY;
        float mx = warp_max(v);
        float au;
        if (mx == -INFINITY) {
            au = 0.f;
        } else {
            float ex = (v == -INFINITY) ? 0.f : __expf(v - mx);
            float sm = warp_sum(ex);
            au = ex / sm;
        }
        float av = au * s_acs[e];
        int s = e * ENT_ + k;
        out[OUT_AU + b * S_ + s] = au;
        out[OUT_AV + b * S_ + s] = av;
    }
}

// ---------------------------------------------------------------------------
// K4: context partials. Block = (entity e, batch b); ENT_=32 units per block.
// Compact nonzero weights via warp ballot, then branch-free loop with 8
// independent LDG.128s batched before FMAs (MLP >= 8 -> HBM-saturating).
// ~75% of rows are exactly zero and never loaded.
// ---------------------------------------------------------------------------
__global__ void k_context(const float* __restrict__ ll, const float* __restrict__ out) {
    int e = blockIdx.x, b = blockIdx.y, t = threadIdx.x;
    __shared__ float sw[ENT_];
    __shared__ int   sidx[ENT_];
    __shared__ int   scnt;
    if (t < 32) {
        float w = out[OUT_AV + b * S_ + e * ENT_ + t];
        unsigned m = __ballot_sync(0xFFFFFFFFu, w != 0.f);
        int pos = __popc(m & ((1u << t) - 1u));
        if (w != 0.f) { sw[pos] = w; sidx[pos] = t; }
        if (t == 0) scnt = __popc(m);
    }
    __syncthreads();
    int cnt = scnt;
    float4 acc = make_float4(0.f, 0.f, 0.f, 0.f);
    const float4* base = (const float4*)ll + (size_t)b * (D_/4) + t;
    const size_t RS = (size_t)B_ * D_ / 4;   // row stride in float4
    int k = 0;
    for (; k + 8 <= cnt; k += 8) {
        float4 v[8];
        #pragma unroll
        for (int u = 0; u < 8; u++)
            v[u] = base[(size_t)(e * ENT_ + sidx[k + u]) * RS];
        #pragma unroll
        for (int u = 0; u < 8; u++) {
            float w = sw[k + u];
            acc.x += w * v[u].x; acc.y += w * v[u].y;
            acc.z += w * v[u].z; acc.w += w * v[u].w;
        }
    }
    for (; k + 4 <= cnt; k += 4) {
        float4 v[4];
        #pragma unroll
        for (int u = 0; u < 4; u++)
            v[u] = base[(size_t)(e * ENT_ + sidx[k + u]) * RS];
        #pragma unroll
        for (int u = 0; u < 4; u++) {
            float w = sw[k + u];
            acc.x += w * v[u].x; acc.y += w * v[u].y;
            acc.z += w * v[u].z; acc.w += w * v[u].w;
        }
    }
    for (; k < cnt; k++) {
        float4 v = base[(size_t)(e * ENT_ + sidx[k]) * RS];
        float w = sw[k];
        acc.x += w * v.x; acc.y += w * v.y; acc.z += w * v.z; acc.w += w * v.w;
    }
    ((float4*)g_cpart)[((size_t)(b * NENT_ + e) * D_) / 4 + t] = acc;
}

// ---------------------------------------------------------------------------
// K5: c[b,d] = sum_e cpart[b,e,d]  (64 partials)
// ---------------------------------------------------------------------------
__global__ void k_reduce() {
    int idx = blockIdx.x * 256 + threadIdx.x;   // 32768
    int b = idx >> 10, d = idx & 1023;
    float s = 0.f;
    #pragma unroll
    for (int e = 0; e < NENT_; e++) s += g_cpart[((size_t)(b * NENT_ + e) << 10) + d];
    g_c[idx] = s;
}

// ---------------------------------------------------------------------------
// K6: attn_h = tanh([c, source] @ W_out^T), M=32 x N-tile=8, K-tiles of 64,
// register-staged prefetch so next tile's global loads overlap compute.
// W_out (8MB) read from DRAM exactly once.
// ---------------------------------------------------------------------------
__global__ void k_gemm(const float* __restrict__ src,
                       const float* __restrict__ Wo,
                       float* __restrict__ out) {
    __shared__ __align__(16) float As[32][68];
    __shared__ __align__(16) float Bs[8][68];
    int t = threadIdx.x;
    int n0 = blockIdx.x * 8;
    int m = t & 31, nl = t >> 5;
    float acc = 0.f;
    float4 a0, a1, b0 = make_float4(0.f, 0.f, 0.f, 0.f);

    auto fetch = [&](int kt, float4& A0, float4& A1, float4& B0) {
        int k0 = kt * 64;
        const float* Asrc = (kt < 16) ? g_c : src;
        int kb = (kt < 16) ? k0 : (k0 - D_);
        int f = t;                          // As: 512 float4 (32 rows x 16)
        A0 = *(const float4*)&Asrc[(f >> 4) * D_ + kb + (f & 15) * 4];
        f = t + 256;
        A1 = *(const float4*)&Asrc[(f >> 4) * D_ + kb + (f & 15) * 4];
        if (t < 128) {                       // Bs: 128 float4 (8 rows x 16)
            f = t;
            B0 = *(const float4*)&Wo[(size_t)(n0 + (f >> 4)) * (2*D_) + k0 + (f & 15) * 4];
        }
    };

    fetch(0, a0, a1, b0);
    #pragma unroll 1
    for (int kt = 0; kt < 32; kt++) {
        int f = t;
        *(float4*)&As[f >> 4][(f & 15) * 4] = a0;
        f = t + 256;
        *(float4*)&As[f >> 4][(f & 15) * 4] = a1;
        if (t < 128) {
            f = t;
            *(float4*)&Bs[f >> 4][(f & 15) * 4] = b0;
        }
        __syncthreads();
        if (kt + 1 < 32) fetch(kt + 1, a0, a1, b0);
        #pragma unroll
        for (int kk = 0; kk < 64; kk += 4) {
            float4 a  = *(const float4*)&As[m][kk];
            float4 bv = *(const float4*)&Bs[nl][kk];
            acc += a.x*bv.x + a.y*bv.y + a.z*bv.z + a.w*bv.w;
        }
        __syncthreads();
    }
    out[OUT_ATTN + m * D_ + n0 + nl] = tanhf(acc);
}

// ---------------------------------------------------------------------------
extern "C" void kernel_launch(void* const* d_in, const int* in_sizes, int n_in,
                              void* d_out, int out_size) {
    const float* src = (const float*)d_in[0];
    const float* hl  = (const float*)d_in[1];
    const float* pe  = (const float*)d_in[2];
    const float* ll  = (const float*)d_in[3];
    const void*  llm = d_in[4];
    const void*  hlm = d_in[5];
    const float* Wu  = (const float*)d_in[6];
    const float* Wc  = (const float*)d_in[7];
    const float* Wo  = (const float*)d_in[8];
    float* out = (float*)d_out;

    k_front<<<5122, 256>>>(src, Wu, Wc, (const unsigned int*)llm, (const unsigned int*)hlm);
    k_align<<<8192 + 260, 256>>>(pe, hl, llm, hlm);
    k_softmax<<<B_, 256>>>(llm, hlm, out);
    k_context<<<dim3(NENT_, B_), 256>>>(ll, out);
    k_reduce<<<B_*D_ / 256, 256>>>();
    k_gemm<<<D_ / 8, 256>>>(src, Wo, out);
}

// round 10
// speedup vs baseline: 1.2866x; 1.0611x over previous
#include <cuda_runtime.h>
#include <math.h>

// HierarchicalAttention — GB300 sm_103a, R10
//
//  0 source (B,D) | 1 high_level_repr (C,B,D) | 2 pos_embs (S,B,UD)
//  3 low_level_repr (S,B,D) f32 268MB | 4 low_level_mask (NENT,B,ENT) bool
//  5 high_level_mask (1,B,C) bool | 6 W_unit (UD,D) | 7 W_chunk (D,D) | 8 W_out (D,2D)
// Output: attn_h (B,D) | align_vectors (B,S) | ac (B,C-1) | au (B,S)

#define B_    32
#define D_    1024
#define UD_   256
#define ENT_  32
#define NENT_ 64
#define S_    2048
#define C_    65

#define OUT_ATTN 0
#define OUT_AV   (B_*D_)
#define OUT_AC   (OUT_AV + B_*S_)
#define OUT_AU   (OUT_AC + B_*(C_-1))

// ---- static scratch ----
__device__ float g_qu[B_*UD_];
__device__ float g_qc[B_*D_];
__device__ float g_align_units[B_*S_];
__device__ float g_align_chunks[B_*C_];
__device__ float g_c[B_*D_];             // atomically accumulated context
__device__ int   g_mode_ll;              // 0=int32, 1=float32, 2=uint8
__device__ int   g_mode_hl;

__device__ __forceinline__ bool read_mask(const void* p, int idx, int mode) {
    if (mode == 0) return ((const int*)p)[idx] != 0;
    if (mode == 1) return ((const float*)p)[idx] != 0.0f;
    return ((const unsigned char*)p)[idx] != 0;
}
__device__ __forceinline__ float warp_sum(float v) {
    #pragma unroll
    for (int o = 16; o; o >>= 1) v += __shfl_xor_sync(0xFFFFFFFFu, v, o);
    return v;
}
__device__ __forceinline__ float warp_max(float v) {
    #pragma unroll
    for (int o = 16; o; o >>= 1) v = fmaxf(v, __shfl_xor_sync(0xFFFFFFFFu, v, o));
    return v;
}

// ---------------------------------------------------------------------------
// K1: projections as a TILED GEMM (W rows read from DRAM exactly once; the
// old warp-per-output form generated 160MB of L2 traffic).
// Combined weight matrix: rows [0,256)=W_unit, [256,1280)=W_chunk.
// Block: M=32 (all b) x N=8 rows, K-tiles of 64 with register prefetch.
// Blocks 160,161 do mask-dtype detection.
// ---------------------------------------------------------------------------
__global__ void k_front(const float* __restrict__ src,
                        const float* __restrict__ Wu,
                        const float* __restrict__ Wc,
                        const unsigned int* __restrict__ llm,
                        const unsigned int* __restrict__ hlm) {
    if (blockIdx.x >= 160) {
        // int32 words are {0,1}; f32 words are {0, 0x3F800000};
        // packed uint8 words hit neither set.
        __shared__ int s_ni, s_nf;
        if (threadIdx.x == 0) { s_ni = 0; s_nf = 0; }
        __syncthreads();
        int which = blockIdx.x - 160;
        const unsigned int* p = which ? hlm : llm;
        int n = which ? (B_*C_ / 4) : (NENT_*B_*ENT_ / 4);
        int ni = 0, nf = 0;
        for (int i = threadIdx.x; i < n; i += blockDim.x) {
            unsigned int w = p[i];
            if (w > 1u) ni = 1;
            if (w != 0u && w != 0x3F800000u) nf = 1;
        }
        if (ni) atomicOr(&s_ni, 1);
        if (nf) atomicOr(&s_nf, 1);
        __syncthreads();
        if (threadIdx.x == 0) {
            int mode = (!s_ni) ? 0 : ((!s_nf) ? 1 : 2);
            if (which) g_mode_hl = mode; else g_mode_ll = mode;
        }
        return;
    }
    __shared__ __align__(16) float As[32][68];
    __shared__ __align__(16) float Bs[8][68];
    int t = threadIdx.x;
    int n0 = blockIdx.x * 8;                 // row block in combined W (uniform matrix)
    const float* W = (n0 < 256) ? Wu : Wc;
    int nb = (n0 < 256) ? n0 : (n0 - 256);
    int m = t & 31, nl = t >> 5;
    float acc = 0.f;
    float4 a0, a1, b0 = make_float4(0.f, 0.f, 0.f, 0.f);

    auto fetch = [&](int kt, float4& A0, float4& A1, float4& B0) {
        int k0 = kt * 64;
        int f = t;
        A0 = *(const float4*)&src[(f >> 4) * D_ + k0 + (f & 15) * 4];
        f = t + 256;
        A1 = *(const float4*)&src[(f >> 4) * D_ + k0 + (f & 15) * 4];
        if (t < 128) {
            f = t;
            B0 = *(const float4*)&W[(size_t)(nb + (f >> 4)) * D_ + k0 + (f & 15) * 4];
        }
    };

    fetch(0, a0, a1, b0);
    #pragma unroll 1
    for (int kt = 0; kt < 16; kt++) {
        int f = t;
        *(float4*)&As[f >> 4][(f & 15) * 4] = a0;
        f = t + 256;
        *(float4*)&As[f >> 4][(f & 15) * 4] = a1;
        if (t < 128) { f = t; *(float4*)&Bs[f >> 4][(f & 15) * 4] = b0; }
        __syncthreads();
        if (kt + 1 < 16) fetch(kt + 1, a0, a1, b0);
        #pragma unroll
        for (int kk = 0; kk < 64; kk += 4) {
            float4 a  = *(const float4*)&As[m][kk];
            float4 bv = *(const float4*)&Bs[nl][kk];
            acc += a.x*bv.x + a.y*bv.y + a.z*bv.z + a.w*bv.w;
        }
        __syncthreads();
    }
    int n = n0 + nl;
    if (n < 256) g_qu[m * UD_ + n] = acc;
    else         g_qc[m * D_ + (n - 256)] = acc;
}

// ---------------------------------------------------------------------------
// K2: alignment dots.
//  blocks [0,2048): units. Block = (entity e, batch b): q_u[b] staged in smem,
//  mask bitmap via ballot, each warp batches loads for 4 rows (8 LDG.128 in
//  flight) before reducing. Masked rows: zero traffic.
//  blocks [2048,2308): chunks — warp per (c,b), D=1024 dot, masked skipped.
// ---------------------------------------------------------------------------
__global__ void k_align(const float* __restrict__ pe,
                        const float* __restrict__ hl,
                        const void* llm, const void* hlm) {
    int lane = threadIdx.x & 31;
    if (blockIdx.x < 2048) {
        int b = blockIdx.x & 31, e = blockIdx.x >> 5;
        int t = threadIdx.x, w = t >> 5;
        __shared__ __align__(16) float sq[UD_];
        __shared__ unsigned s_bm;
        if (t < 64) ((float4*)sq)[t] = ((const float4*)g_qu)[b * (UD_/4) + t];
        if (w == 0) {
            bool mk = read_mask(llm, e * (B_*ENT_) + b * ENT_ + lane, g_mode_ll);
            unsigned bm = __ballot_sync(0xFFFFFFFFu, mk);
            if (lane == 0) s_bm = bm;
        }
        __syncthreads();
        unsigned bm = s_bm;
        float4 q0 = ((const float4*)sq)[lane];
        float4 q1 = ((const float4*)sq)[lane + 32];
        const float4* peb = (const float4*)pe + (size_t)b * (UD_/4) + lane;
        const size_t RS = (size_t)B_ * UD_ / 4;
        int s0 = e * ENT_ + w * 4;
        float4 v[4][2];
        #pragma unroll
        for (int r = 0; r < 4; r++) {
            if (!((bm >> (w*4 + r)) & 1u)) {
                const float4* p = peb + (size_t)(s0 + r) * RS;
                v[r][0] = p[0];
                v[r][1] = p[32];
            }
        }
        #pragma unroll
        for (int r = 0; r < 4; r++) {
            if (!((bm >> (w*4 + r)) & 1u)) {
                float acc = v[r][0].x*q0.x + v[r][0].y*q0.y + v[r][0].z*q0.z + v[r][0].w*q0.w
                          + v[r][1].x*q1.x + v[r][1].y*q1.y + v[r][1].z*q1.z + v[r][1].w*q1.w;
                acc = warp_sum(acc);
                if (lane == 0) g_align_units[b * S_ + s0 + r] = acc;
            }
        }
    } else {
        int g = ((blockIdx.x - 2048) * 256 + threadIdx.x) >> 5;
        int b = g & 31, c = g >> 5;
        if (c >= C_) return;
        if (c > 0 && read_mask(hlm, b * C_ + c, g_mode_hl)) return;
        const float4* p = (const float4*)(hl) + ((size_t)c * B_ + b) * (D_/4);
        const float4* q = (const float4*)(g_qc) + b * (D_/4);
        float acc = 0.f;
        #pragma unroll
        for (int it = 0; it < 8; it++) {
            float4 x = p[lane + it*32], y = q[lane + it*32];
            acc += x.x*y.x + x.y*y.y + x.z*y.z + x.w*y.w;
        }
        acc = warp_sum(acc);
        if (lane == 0) g_align_chunks[b * C_ + c] = acc;
    }
}

// ---------------------------------------------------------------------------
// K3: fused masked softmaxes + align_vectors; also zeroes g_c for K4 atomics.
// ---------------------------------------------------------------------------
__global__ void k_softmax(const void* llm, const void* hlm, float* __restrict__ out) {
    int b = blockIdx.x, t = threadIdx.x;
    __shared__ float s_raw[C_];
    __shared__ float s_acs[C_-1];

    ((float4*)g_c)[b * (D_/4) + t] = make_float4(0.f, 0.f, 0.f, 0.f);

    int mhl = g_mode_hl, mll = g_mode_ll;
    if (t < C_) {
        float v = g_align_chunks[b * C_ + t];
        if (read_mask(hlm, b * C_ + t, mhl)) v = -INFINITY;
        s_raw[t] = v;
    }
    __syncthreads();
    if (t == 0) {
        float mx = -INFINITY;
        for (int c = 0; c < C_; c++) mx = fmaxf(mx, s_raw[c]);
        float sum = 0.f;
        for (int c = 0; c < C_; c++) {
            float e = (s_raw[c] == -INFINITY) ? 0.f : __expf(s_raw[c] - mx);
            s_raw[c] = e; sum += e;
        }
        float inv = 1.f / sum;
        for (int c = 1; c < C_; c++) {
            float v = s_raw[c] * inv;
            s_acs[c-1] = v;
            out[OUT_AC + b * (C_-1) + (c-1)] = v;
        }
    }
    __syncthreads();

    int w = t >> 5, k = t & 31;
    for (int e = w; e < NENT_; e += 8) {
        float v = g_align_units[b * S_ + e * ENT_ + k];
        if (read_mask(llm, e * (B_*ENT_) + b * ENT_ + k, mll)) v = -INFINITY;
        float mx = warp_max(v);
        float au;
        if (mx == -INFINITY) {
            au = 0.f;
        } else {
            float ex = (v == -INFINITY) ? 0.f : __expf(v - mx);
            float sm = warp_sum(ex);
            au = ex / sm;
        }
        float av = au * s_acs[e];
        int s = e * ENT_ + k;
        out[OUT_AU + b * S_ + s] = au;
        out[OUT_AV + b * S_ + s] = av;
    }
}

// ---------------------------------------------------------------------------
// K4: context. Block = (entity e, batch b, D-half); 128 threads x float4.
// Ballot-compacted nonzero weights, 8 LDG.128 batched before FMAs.
// cnt==0 blocks (~50%) exit with ZERO traffic; partial sums go straight into
// g_c via RED.ADD.F32 (no k_reduce pass, no 16MB partial round-trip).
// ---------------------------------------------------------------------------
__global__ void k_context(const float* __restrict__ ll, const float* __restrict__ out) {
    int e = blockIdx.x, b = blockIdx.y, half = blockIdx.z, t = threadIdx.x;
    __shared__ float sw[ENT_];
    __shared__ int   sidx[ENT_];
    __shared__ int   scnt;
    if (t < 32) {
        float w = out[OUT_AV + b * S_ + e * ENT_ + t];
        unsigned m = __ballot_sync(0xFFFFFFFFu, w != 0.f);
        int pos = __popc(m & ((1u << t) - 1u));
        if (w != 0.f) { sw[pos] = w; sidx[pos] = t; }
        if (t == 0) scnt = __popc(m);
    }
    __syncthreads();
    int cnt = scnt;
    if (cnt == 0) return;
    float4 acc = make_float4(0.f, 0.f, 0.f, 0.f);
    const float4* base = (const float4*)ll + (size_t)b * (D_/4) + half * 128 + t;
    const size_t RS = (size_t)B_ * D_ / 4;
    int k = 0;
    for (; k + 8 <= cnt; k += 8) {
        float4 v[8];
        #pragma unroll
        for (int u = 0; u < 8; u++)
            v[u] = base[(size_t)(e * ENT_ + sidx[k + u]) * RS];
        #pragma unroll
        for (int u = 0; u < 8; u++) {
            float w = sw[k + u];
            acc.x += w * v[u].x; acc.y += w * v[u].y;
            acc.z += w * v[u].z; acc.w += w * v[u].w;
        }
    }
    for (; k + 4 <= cnt; k += 4) {
        float4 v[4];
        #pragma unroll
        for (int u = 0; u < 4; u++)
            v[u] = base[(size_t)(e * ENT_ + sidx[k + u]) * RS];
        #pragma unroll
        for (int u = 0; u < 4; u++) {
            float w = sw[k + u];
            acc.x += w * v[u].x; acc.y += w * v[u].y;
            acc.z += w * v[u].z; acc.w += w * v[u].w;
        }
    }
    for (; k < cnt; k++) {
        float4 v = base[(size_t)(e * ENT_ + sidx[k]) * RS];
        float w = sw[k];
        acc.x += w * v.x; acc.y += w * v.y; acc.z += w * v.z; acc.w += w * v.w;
    }
    float* dst = &g_c[b * D_ + half * 512 + t * 4];
    atomicAdd(dst + 0, acc.x);
    atomicAdd(dst + 1, acc.y);
    atomicAdd(dst + 2, acc.z);
    atomicAdd(dst + 3, acc.w);
}

// ---------------------------------------------------------------------------
// K5: attn_h = tanh([c, source] @ W_out^T). M=32 x N-tile=8, register-staged
// prefetch; W_out (8MB) read from DRAM exactly once.
// ---------------------------------------------------------------------------
__global__ void k_gemm(const float* __restrict__ src,
                       const float* __restrict__ Wo,
                       float* __restrict__ out) {
    __shared__ __align__(16) float As[32][68];
    __shared__ __align__(16) float Bs[8][68];
    int t = threadIdx.x;
    int n0 = blockIdx.x * 8;
    int m = t & 31, nl = t >> 5;
    float acc = 0.f;
    float4 a0, a1, b0 = make_float4(0.f, 0.f, 0.f, 0.f);

    auto fetch = [&](int kt, float4& A0, float4& A1, float4& B0) {
        int k0 = kt * 64;
        const float* Asrc = (kt < 16) ? g_c : src;
        int kb = (kt < 16) ? k0 : (k0 - D_);
        int f = t;
        A0 = *(const float4*)&Asrc[(f >> 4) * D_ + kb + (f & 15) * 4];
        f = t + 256;
        A1 = *(const float4*)&Asrc[(f >> 4) * D_ + kb + (f & 15) * 4];
        if (t < 128) {
            f = t;
            B0 = *(const float4*)&Wo[(size_t)(n0 + (f >> 4)) * (2*D_) + k0 + (f & 15) * 4];
        }
    };

    fetch(0, a0, a1, b0);
    #pragma unroll 1
    for (int kt = 0; kt < 32; kt++) {
        int f = t;
        *(float4*)&As[f >> 4][(f & 15) * 4] = a0;
        f = t + 256;
        *(float4*)&As[f >> 4][(f & 15) * 4] = a1;
        if (t < 128) { f = t; *(float4*)&Bs[f >> 4][(f & 15) * 4] = b0; }
        __syncthreads();
        if (kt + 1 < 32) fetch(kt + 1, a0, a1, b0);
        #pragma unroll
        for (int kk = 0; kk < 64; kk += 4) {
            float4 a  = *(const float4*)&As[m][kk];
            float4 bv = *(const float4*)&Bs[nl][kk];
            acc += a.x*bv.x + a.y*bv.y + a.z*bv.z + a.w*bv.w;
        }
        __syncthreads();
    }
    out[OUT_ATTN + m * D_ + n0 + nl] = tanhf(acc);
}

// ---------------------------------------------------------------------------
extern "C" void kernel_launch(void* const* d_in, const int* in_sizes, int n_in,
                              void* d_out, int out_size) {
    const float* src = (const float*)d_in[0];
    const float* hl  = (const float*)d_in[1];
    const float* pe  = (const float*)d_in[2];
    const float* ll  = (const float*)d_in[3];
    const void*  llm = d_in[4];
    const void*  hlm = d_in[5];
    const float* Wu  = (const float*)d_in[6];
    const float* Wc  = (const float*)d_in[7];
    const float* Wo  = (const float*)d_in[8];
    float* out = (float*)d_out;

    k_front<<<162, 256>>>(src, Wu, Wc, (const unsigned int*)llm, (const unsigned int*)hlm);
    k_align<<<2048 + 260, 256>>>(pe, hl, llm, hlm);
    k_softmax<<<B_, 256>>>(llm, hlm, out);
    k_context<<<dim3(NENT_, B_, 2), 128>>>(ll, out);
    k_gemm<<<D_ / 8, 256>>>(src, Wo, out);
}

// round 11
// speedup vs baseline: 1.5849x; 1.2318x over previous
#include <cuda_runtime.h>
#include <math.h>

// HierarchicalAttention — GB300 sm_103a, R11
// 4 launches: front(proj + detect + zero + src-half-GEMM) -> align(+both
// softmaxes) -> context(av + atomics) -> gemm_fin(tanh epilogue).
//
//  0 source (B,D) | 1 high_level_repr (C,B,D) | 2 pos_embs (S,B,UD)
//  3 low_level_repr (S,B,D) f32 268MB | 4 low_level_mask (NENT,B,ENT) bool
//  5 high_level_mask (1,B,C) bool | 6 W_unit (UD,D) | 7 W_chunk (D,D) | 8 W_out (D,2D)
// Output: attn_h (B,D) | align_vectors (B,S) | ac (B,C-1) | au (B,S)

#define B_    32
#define D_    1024
#define UD_   256
#define ENT_  32
#define NENT_ 64
#define S_    2048
#define C_    65

#define OUT_ATTN 0
#define OUT_AV   (B_*D_)
#define OUT_AC   (OUT_AV + B_*S_)
#define OUT_AU   (OUT_AC + B_*(C_-1))

// ---- static scratch ----
__device__ float g_qu[B_*UD_];
__device__ float g_qc[B_*D_];
__device__ float g_acs[B_*NENT_];        // chunk softmax (chunks 1..64)
__device__ float g_c[B_*D_];             // atomically accumulated context
__device__ float g_hpart[B_*D_];         // src-half of output GEMM (pre-tanh)
__device__ int   g_mode_ll;              // 0=int32, 1=float32, 2=uint8
__device__ int   g_mode_hl;

__device__ __forceinline__ bool read_mask(const void* p, int idx, int mode) {
    if (mode == 0) return ((const int*)p)[idx] != 0;
    if (mode == 1) return ((const float*)p)[idx] != 0.0f;
    return ((const unsigned char*)p)[idx] != 0;
}
__device__ __forceinline__ float warp_sum(float v) {
    #pragma unroll
    for (int o = 16; o; o >>= 1) v += __shfl_xor_sync(0xFFFFFFFFu, v, o);
    return v;
}
__device__ __forceinline__ float warp_max(float v) {
    #pragma unroll
    for (int o = 16; o; o >>= 1) v = fmaxf(v, __shfl_xor_sync(0xFFFFFFFFu, v, o));
    return v;
}

// ---------------------------------------------------------------------------
// Shared tiled-GEMM helper: 32(M=B) x 8(N) tile, 16 K-tiles of 64, register
// prefetch, two accumulators (halves the 64-FFMA dependency chain that bounds
// the inner loop at 1 block/SM). A is 32xD_ row-major; W8 = 8 rows, stride ws.
// Thread t owns output (m = t&31, nl = t>>5).
// ---------------------------------------------------------------------------
__device__ __forceinline__ float tile_gemm16(const float* __restrict__ A,
                                             const float* __restrict__ W8,
                                             int ws) {
    __shared__ __align__(16) float As[32][68];
    __shared__ __align__(16) float Bs[8][68];
    int t = threadIdx.x;
    int m = t & 31, nl = t >> 5;
    float acc0 = 0.f, acc1 = 0.f;
    float4 a0, a1, b0 = make_float4(0.f, 0.f, 0.f, 0.f);

    auto fetch = [&](int kt) {
        int k0 = kt * 64;
        int f = t;
        a0 = *(const float4*)&A[(f >> 4) * D_ + k0 + (f & 15) * 4];
        f = t + 256;
        a1 = *(const float4*)&A[(f >> 4) * D_ + k0 + (f & 15) * 4];
        if (t < 128) {
            f = t;
            b0 = *(const float4*)&W8[(size_t)(f >> 4) * ws + k0 + (f & 15) * 4];
        }
    };

    fetch(0);
    #pragma unroll 1
    for (int kt = 0; kt < 16; kt++) {
        int f = t;
        *(float4*)&As[f >> 4][(f & 15) * 4] = a0;
        f = t + 256;
        *(float4*)&As[f >> 4][(f & 15) * 4] = a1;
        if (t < 128) { f = t; *(float4*)&Bs[f >> 4][(f & 15) * 4] = b0; }
        __syncthreads();
        if (kt + 1 < 16) fetch(kt + 1);
        #pragma unroll
        for (int kk = 0; kk < 64; kk += 8) {
            float4 a  = *(const float4*)&As[m][kk];
            float4 bv = *(const float4*)&Bs[nl][kk];
            acc0 += a.x*bv.x + a.y*bv.y + a.z*bv.z + a.w*bv.w;
            float4 a2 = *(const float4*)&As[m][kk + 4];
            float4 b2 = *(const float4*)&Bs[nl][kk + 4];
            acc1 += a2.x*b2.x + a2.y*b2.y + a2.z*b2.z + a2.w*b2.w;
        }
        __syncthreads();
    }
    return acc0 + acc1;
}

// ---------------------------------------------------------------------------
// K1 front — all mutually independent work in one launch:
//  [0,160):   projections GEMM (q_u rows 0..255, q_c rows 256..1279)
//  [160,162): mask dtype detection
//  [162,164): zero g_c for context atomics
//  [164,292): SOURCE HALF of output GEMM: hpart = src @ Wo[:,1024:2048]^T
//             (depends only on inputs -> pulled off the critical path tail)
// ---------------------------------------------------------------------------
__global__ void k_front(const float* __restrict__ src,
                        const float* __restrict__ Wu,
                        const float* __restrict__ Wc,
                        const float* __restrict__ Wo,
                        const unsigned int* __restrict__ llm,
                        const unsigned int* __restrict__ hlm) {
    int bx = blockIdx.x, t = threadIdx.x;
    if (bx >= 160 && bx < 162) {
        // int32 words are {0,1}; f32 words are {0,0x3F800000}; packed uint8
        // words hit neither set (random 0/1 data).
        __shared__ int s_ni, s_nf;
        if (t == 0) { s_ni = 0; s_nf = 0; }
        __syncthreads();
        int which = bx - 160;
        const unsigned int* p = which ? hlm : llm;
        int n = which ? (B_*C_ / 4) : (NENT_*B_*ENT_ / 4);
        int ni = 0, nf = 0;
        for (int i = t; i < n; i += blockDim.x) {
            unsigned int w = p[i];
            if (w > 1u) ni = 1;
            if (w != 0u && w != 0x3F800000u) nf = 1;
        }
        if (ni) atomicOr(&s_ni, 1);
        if (nf) atomicOr(&s_nf, 1);
        __syncthreads();
        if (t == 0) {
            int mode = (!s_ni) ? 0 : ((!s_nf) ? 1 : 2);
            if (which) g_mode_hl = mode; else g_mode_ll = mode;
        }
        return;
    }
    if (bx >= 162 && bx < 164) {
        float4* p = (float4*)g_c + (bx - 162) * 4096;
        #pragma unroll
        for (int i = 0; i < 16; i++) p[t + i * 256] = make_float4(0.f, 0.f, 0.f, 0.f);
        return;
    }
    int m = t & 31, nl = t >> 5;
    if (bx < 160) {
        int n0 = bx * 8;
        const float* W = (n0 < 256) ? Wu : Wc;
        int nb = (n0 < 256) ? n0 : (n0 - 256);
        float acc = tile_gemm16(src, W + (size_t)nb * D_, D_);
        int n = n0 + nl;
        if (n < 256) g_qu[m * UD_ + n] = acc;
        else         g_qc[m * D_ + (n - 256)] = acc;
    } else {
        int n0 = (bx - 164) * 8;
        float acc = tile_gemm16(src, Wo + (size_t)n0 * (2*D_) + D_, 2*D_);
        g_hpart[m * D_ + n0 + nl] = acc;
    }
}

// ---------------------------------------------------------------------------
// K2 align — both alignment dots AND both softmaxes:
//  [0,2048): unit blocks (e,b): q_u staged in smem, masked rows skipped (zero
//            traffic), 8 LDG.128 batched per warp, then the per-entity masked
//            softmax is BLOCK-LOCAL -> done here; writes au to out.
//  [2048,2080): chunk blocks (one per b): all 65 chunk dots (masked skipped)
//            + chunk softmax; writes ac to out and g_acs.
// ---------------------------------------------------------------------------
__global__ void k_align(const float* __restrict__ pe,
                        const float* __restrict__ hl,
                        const void* llm, const void* hlm,
                        float* __restrict__ out) {
    int t = threadIdx.x, w = t >> 5, lane = t & 31;
    if (blockIdx.x < 2048) {
        int b = blockIdx.x & 31, e = blockIdx.x >> 5;
        __shared__ __align__(16) float sq[UD_];
        __shared__ float s_val[ENT_];
        __shared__ unsigned s_bm;
        if (t < 64) ((float4*)sq)[t] = ((const float4*)g_qu)[b * (UD_/4) + t];
        if (w == 0) {
            bool mk = read_mask(llm, e * (B_*ENT_) + b * ENT_ + lane, g_mode_ll);
            unsigned bm = __ballot_sync(0xFFFFFFFFu, mk);
            if (lane == 0) s_bm = bm;
        }
        __syncthreads();
        unsigned bm = s_bm;
        float4 q0 = ((const float4*)sq)[lane];
        float4 q1 = ((const float4*)sq)[lane + 32];
        const float4* peb = (const float4*)pe + (size_t)b * (UD_/4) + lane;
        const size_t RS = (size_t)B_ * UD_ / 4;
        int s0 = e * ENT_ + w * 4;
        float4 v[4][2];
        #pragma unroll
        for (int r = 0; r < 4; r++) {
            if (!((bm >> (w*4 + r)) & 1u)) {
                const float4* p = peb + (size_t)(s0 + r) * RS;
                v[r][0] = p[0];
                v[r][1] = p[32];
            }
        }
        #pragma unroll
        for (int r = 0; r < 4; r++) {
            if (!((bm >> (w*4 + r)) & 1u)) {
                float acc = v[r][0].x*q0.x + v[r][0].y*q0.y + v[r][0].z*q0.z + v[r][0].w*q0.w
                          + v[r][1].x*q1.x + v[r][1].y*q1.y + v[r][1].z*q1.z + v[r][1].w*q1.w;
                acc = warp_sum(acc);
                if (lane == 0) s_val[w*4 + r] = acc;
            } else if (lane == 0) {
                s_val[w*4 + r] = -INFINITY;
            }
        }
        __syncthreads();
        if (w == 0) {
            float vv = s_val[lane];
            float mx = warp_max(vv);
            float au;
            if (mx == -INFINITY) {
                au = 0.f;                       // all-masked entity
            } else {
                float ex = (vv == -INFINITY) ? 0.f : __expf(vv - mx);
                float sm = warp_sum(ex);
                au = ex / sm;
            }
            out[OUT_AU + b * S_ + e * ENT_ + lane] = au;
        }
    } else {
        int b = blockIdx.x - 2048;
        __shared__ __align__(16) float sqc[D_];
        __shared__ float s_sc[C_];
        ((float4*)sqc)[t] = ((const float4*)g_qc)[b * (D_/4) + t];
        __syncthreads();
        int mhl = g_mode_hl;
        for (int c = w; c < C_; c += 8) {
            if (read_mask(hlm, b * C_ + c, mhl)) {
                if (lane == 0) s_sc[c] = -INFINITY;
                continue;
            }
            const float4* p = (const float4*)hl + ((size_t)c * B_ + b) * (D_/4);
            float acc = 0.f;
            #pragma unroll
            for (int it = 0; it < 8; it++) {
                float4 x = p[lane + it*32];
                float4 y = ((const float4*)sqc)[lane + it*32];
                acc += x.x*y.x + x.y*y.y + x.z*y.z + x.w*y.w;
            }
            acc = warp_sum(acc);
            if (lane == 0) s_sc[c] = acc;
        }
        __syncthreads();
        if (t == 0) {
            float mx = -INFINITY;
            for (int c = 0; c < C_; c++) mx = fmaxf(mx, s_sc[c]);
            float sum = 0.f;
            for (int c = 0; c < C_; c++) {
                float e = (s_sc[c] == -INFINITY) ? 0.f : __expf(s_sc[c] - mx);
                s_sc[c] = e; sum += e;
            }
            float inv = 1.f / sum;
            for (int c = 1; c < C_; c++) {
                float vv = s_sc[c] * inv;
                g_acs[b * NENT_ + (c-1)] = vv;
                out[OUT_AC + b * (C_-1) + (c-1)] = vv;
            }
        }
    }
}

// ---------------------------------------------------------------------------
// K3 context. Block = (entity e, batch b, D-half); computes av = au*ac[e]
// itself (writes the av output), ballot-compacts nonzero weights, 8 LDG.128
// batched before FMAs, RED.ADD.F32 partial sums into g_c. ~75% of rows are
// exactly zero and never loaded; cnt==0 blocks exit with zero ll traffic.
// ---------------------------------------------------------------------------
__global__ void k_context(const float* __restrict__ ll, float* __restrict__ out) {
    int e = blockIdx.x, b = blockIdx.y, half = blockIdx.z, t = threadIdx.x;
    __shared__ float sw[ENT_];
    __shared__ int   sidx[ENT_];
    __shared__ int   scnt;
    float ac = g_acs[b * NENT_ + e];
    if (t < 32) {
        float au = out[OUT_AU + b * S_ + e * ENT_ + t];
        float av = au * ac;
        if (half == 0) out[OUT_AV + b * S_ + e * ENT_ + t] = av;
        unsigned m = __ballot_sync(0xFFFFFFFFu, av != 0.f);
        int pos = __popc(m & ((1u << t) - 1u));
        if (av != 0.f) { sw[pos] = av; sidx[pos] = t; }
        if (t == 0) scnt = __popc(m);
    }
    __syncthreads();
    int cnt = scnt;
    if (cnt == 0) return;
    float4 acc = make_float4(0.f, 0.f, 0.f, 0.f);
    const float4* base = (const float4*)ll + (size_t)b * (D_/4) + half * 128 + t;
    const size_t RS = (size_t)B_ * D_ / 4;
    int k = 0;
    for (; k + 8 <= cnt; k += 8) {
        float4 v[8];
        #pragma unroll
        for (int u = 0; u < 8; u++)
            v[u] = base[(size_t)(e * ENT_ + sidx[k + u]) * RS];
        #pragma unroll
        for (int u = 0; u < 8; u++) {
            float w = sw[k + u];
            acc.x += w * v[u].x; acc.y += w * v[u].y;
            acc.z += w * v[u].z; acc.w += w * v[u].w;
        }
    }
    for (; k + 4 <= cnt; k += 4) {
        float4 v[4];
        #pragma unroll
        for (int u = 0; u < 4; u++)
            v[u] = base[(size_t)(e * ENT_ + sidx[k + u]) * RS];
        #pragma unroll
        for (int u = 0; u < 4; u++) {
            float w = sw[k + u];
            acc.x += w * v[u].x; acc.y += w * v[u].y;
            acc.z += w * v[u].z; acc.w += w * v[u].w;
        }
    }
    for (; k < cnt; k++) {
        float4 v = base[(size_t)(e * ENT_ + sidx[k]) * RS];
        float w = sw[k];
        acc.x += w * v.x; acc.y += w * v.y; acc.z += w * v.z; acc.w += w * v.w;
    }
    float* dst = &g_c[b * D_ + half * 512 + t * 4];
    atomicAdd(dst + 0, acc.x);
    atomicAdd(dst + 1, acc.y);
    atomicAdd(dst + 2, acc.z);
    atomicAdd(dst + 3, acc.w);
}

// ---------------------------------------------------------------------------
// K4 epilogue: attn_h = tanh(c @ Wo[:, :1024]^T + hpart). Only 16 K-tiles —
// the src half already ran inside k_front.
// ---------------------------------------------------------------------------
__global__ void k_gemm_fin(const float* __restrict__ Wo, float* __restrict__ out) {
    int t = threadIdx.x;
    int n0 = blockIdx.x * 8;
    int m = t & 31, nl = t >> 5;
    float acc = tile_gemm16(g_c, Wo + (size_t)n0 * (2*D_), 2*D_);
    out[OUT_ATTN + m * D_ + n0 + nl] = tanhf(acc + g_hpart[m * D_ + n0 + nl]);
}

// ---------------------------------------------------------------------------
extern "C" void kernel_launch(void* const* d_in, const int* in_sizes, int n_in,
                              void* d_out, int out_size) {
    const float* src = (const float*)d_in[0];
    const float* hl  = (const float*)d_in[1];
    const float* pe  = (const float*)d_in[2];
    const float* ll  = (const float*)d_in[3];
    const void*  llm = d_in[4];
    const void*  hlm = d_in[5];
    const float* Wu  = (const float*)d_in[6];
    const float* Wc  = (const float*)d_in[7];
    const float* Wo  = (const float*)d_in[8];
    float* out = (float*)d_out;

    k_front<<<292, 256>>>(src, Wu, Wc, Wo,
                          (const unsigned int*)llm, (const unsigned int*)hlm);
    k_align<<<2048 + 32, 256>>>(pe, hl, llm, hlm, out);
    k_context<<<dim3(NENT_, B_, 2), 128>>>(ll, out);
    k_gemm_fin<<<128, 256>>>(Wo, out);
}

// round 12
// speedup vs baseline: 1.6347x; 1.0314x over previous
#include <cuda_runtime.h>
#include <math.h>

// HierarchicalAttention — GB300 sm_103a, R12
// 5 launches: front(proj + src-half GEMM, K-split partials, detect)
//          -> align(dots + both softmaxes + zero g_c)
//          -> context(sparse weighted sum, atomics into g_c)
//          -> gemm_c(c-half GEMM, K-split partials)
//          -> tanh(sum partials + tanh)
//
// Output: attn_h (B,D) | align_vectors (B,S) | ac (B,C-1) | au (B,S)

#define B_    32
#define D_    1024
#define UD_   256
#define ENT_  32
#define NENT_ 64
#define S_    2048
#define C_    65
#define KSPL  4

#define OUT_ATTN 0
#define OUT_AV   (B_*D_)
#define OUT_AC   (OUT_AV + B_*S_)
#define OUT_AU   (OUT_AC + B_*(C_-1))

// ---- static scratch ----
__device__ float g_qp[KSPL][B_*(UD_+D_)];  // proj partials: [m*1280 + n] (n<256 qu, else qc)
__device__ float g_hs[KSPL][B_*D_];        // src-half of output GEMM, partials
__device__ float g_hc[KSPL][B_*D_];        // c-half of output GEMM, partials
__device__ float g_acs[B_*NENT_];          // chunk softmax (chunks 1..64)
__device__ float g_c[B_*D_];               // atomically accumulated context
__device__ int   g_mode_ll;                // 0=int32, 1=float32, 2=uint8
__device__ int   g_mode_hl;

__device__ __forceinline__ bool read_mask(const void* p, int idx, int mode) {
    if (mode == 0) return ((const int*)p)[idx] != 0;
    if (mode == 1) return ((const float*)p)[idx] != 0.0f;
    return ((const unsigned char*)p)[idx] != 0;
}
__device__ __forceinline__ float warp_sum(float v) {
    #pragma unroll
    for (int o = 16; o; o >>= 1) v += __shfl_xor_sync(0xFFFFFFFFu, v, o);
    return v;
}
__device__ __forceinline__ float warp_max(float v) {
    #pragma unroll
    for (int o = 16; o; o >>= 1) v = fmaxf(v, __shfl_xor_sync(0xFFFFFFFFu, v, o));
    return v;
}

// ---------------------------------------------------------------------------
// GEMM primitive: 32(M)x32(N) output tile over `ntiles` K-tiles of 64.
// 128 threads: lane = m (M == warpsize), warp owns 8 n-columns.
// Inner chunk: 1 As LDS.128 + 8 broadcast Bs LDS.128 + 32 FFMA
//   -> As crossbar bytes amortized over 8 outputs (vs 1 before: the 8x
//      redundancy that made R11's GEMMs L1-bound at occ 12% is gone).
// dst[m*ldd + n] (plain stores to a per-K-split partial buffer; no atomics).
// ---------------------------------------------------------------------------
__device__ __forceinline__ void gemm_tile(const float* __restrict__ A, int lda,
                                          const float* __restrict__ Bn, int ldb,
                                          int k0, int ntiles,
                                          float* __restrict__ dst, int ldd) {
    __shared__ __align__(16) float As[32][68];
    __shared__ __align__(16) float Bs[32][68];
    int t = threadIdx.x, lane = t & 31, wid = t >> 5;
    float acc[8];
    #pragma unroll
    for (int j = 0; j < 8; j++) acc[j] = 0.f;

    for (int kt = 0; kt < ntiles; kt++) {
        int kk0 = k0 + kt * 64;
        #pragma unroll
        for (int i = 0; i < 4; i++) {
            int idx = t + i * 128;              // 512 float4 each
            int r = idx >> 4, c = (idx & 15) * 4;
            *(float4*)&As[r][c] = *(const float4*)&A [(size_t)r * lda + kk0 + c];
            *(float4*)&Bs[r][c] = *(const float4*)&Bn[(size_t)r * ldb + kk0 + c];
        }
        __syncthreads();
        #pragma unroll
        for (int i = 0; i < 16; i++) {
            float4 a = *(const float4*)&As[lane][i * 4];
            #pragma unroll
            for (int j = 0; j < 8; j++) {
                float4 b = *(const float4*)&Bs[wid * 8 + j][i * 4];
                acc[j] += a.x*b.x + a.y*b.y + a.z*b.z + a.w*b.w;
            }
        }
        __syncthreads();
    }
    #pragma unroll
    for (int j = 0; j < 8; j++)
        dst[lane * ldd + wid * 8 + j] = acc[j];
}

// ---------------------------------------------------------------------------
// K1 front:
//  [0,160):   proj GEMM  (40 n-groups x 4 K-splits) -> g_qp[ks]
//  [160,288): src-half of output GEMM (32 n-groups x 4 K-splits) -> g_hs[ks]
//  [288,290): mask dtype detection
// ---------------------------------------------------------------------------
__global__ void k_front(const float* __restrict__ src,
                        const float* __restrict__ Wu,
                        const float* __restrict__ Wc,
                        const float* __restrict__ Wo,
                        const unsigned int* __restrict__ llm,
                        const unsigned int* __restrict__ hlm) {
    int bx = blockIdx.x, t = threadIdx.x;
    if (bx >= 288) {
        // int32 words are {0,1}; f32 words are {0,0x3F800000}; packed uint8
        // words hit neither set (random 0/1 data).
        __shared__ int s_ni, s_nf;
        if (t == 0) { s_ni = 0; s_nf = 0; }
        __syncthreads();
        int which = bx - 288;
        const unsigned int* p = which ? hlm : llm;
        int n = which ? (B_*C_ / 4) : (NENT_*B_*ENT_ / 4);
        int ni = 0, nf = 0;
        for (int i = t; i < n; i += blockDim.x) {
            unsigned int w = p[i];
            if (w > 1u) ni = 1;
            if (w != 0u && w != 0x3F800000u) nf = 1;
        }
        if (ni) atomicOr(&s_ni, 1);
        if (nf) atomicOr(&s_nf, 1);
        __syncthreads();
        if (t == 0) {
            int mode = (!s_ni) ? 0 : ((!s_nf) ? 1 : 2);
            if (which) g_mode_hl = mode; else g_mode_ll = mode;
        }
        return;
    }
    if (bx < 160) {
        int g = bx >> 2, ks = bx & 3;
        int n0 = g * 32;
        const float* Bn;
        if (n0 < 256) Bn = Wu + (size_t)n0 * D_;
        else          Bn = Wc + (size_t)(n0 - 256) * D_;
        gemm_tile(src, D_, Bn, D_, ks * 256, 4, &g_qp[ks][n0], UD_ + D_);
    } else {
        int h = bx - 160;
        int g = h >> 2, ks = h & 3;
        int n0 = g * 32;
        gemm_tile(src, D_, Wo + (size_t)n0 * (2*D_) + D_, 2*D_,
                  ks * 256, 4, &g_hs[ks][n0], D_);
    }
}

// ---------------------------------------------------------------------------
// K2 align — alignment dots + both softmaxes; first 256 unit blocks also
// zero g_c for K3's atomics.
//  [0,2048): unit blocks (e,b): q_u (= sum of proj partials) staged in smem,
//            masked rows skipped (zero traffic), batched LDG.128, block-local
//            per-entity masked softmax; writes au to out.
//  [2048,2080): chunk blocks (one per b): 65 chunk dots + softmax; writes ac.
// ---------------------------------------------------------------------------
__global__ void k_align(const float* __restrict__ pe,
                        const float* __restrict__ hl,
                        const void* llm, const void* hlm,
                        float* __restrict__ out) {
    int t = threadIdx.x, w = t >> 5, lane = t & 31;
    if (blockIdx.x < 2048) {
        int b = blockIdx.x & 31, e = blockIdx.x >> 5;
        if (blockIdx.x < 256 && t < 32)
            ((float4*)g_c)[blockIdx.x * 32 + t] = make_float4(0.f, 0.f, 0.f, 0.f);
        __shared__ __align__(16) float sq[UD_];
        __shared__ float s_val[ENT_];
        __shared__ unsigned s_bm;
        if (t < 64) {
            float4 q = make_float4(0.f, 0.f, 0.f, 0.f);
            #pragma unroll
            for (int ks = 0; ks < KSPL; ks++) {
                float4 p = ((const float4*)g_qp[ks])[b * ((UD_+D_)/4) + t];
                q.x += p.x; q.y += p.y; q.z += p.z; q.w += p.w;
            }
            ((float4*)sq)[t] = q;
        }
        if (w == 0) {
            bool mk = read_mask(llm, e * (B_*ENT_) + b * ENT_ + lane, g_mode_ll);
            unsigned bm = __ballot_sync(0xFFFFFFFFu, mk);
            if (lane == 0) s_bm = bm;
        }
        __syncthreads();
        unsigned bm = s_bm;
        float4 q0 = ((const float4*)sq)[lane];
        float4 q1 = ((const float4*)sq)[lane + 32];
        const float4* peb = (const float4*)pe + (size_t)b * (UD_/4) + lane;
        const size_t RS = (size_t)B_ * UD_ / 4;
        int s0 = e * ENT_ + w * 4;
        float4 v[4][2];
        #pragma unroll
        for (int r = 0; r < 4; r++) {
            if (!((bm >> (w*4 + r)) & 1u)) {
                const float4* p = peb + (size_t)(s0 + r) * RS;
                v[r][0] = p[0];
                v[r][1] = p[32];
            }
        }
        #pragma unroll
        for (int r = 0; r < 4; r++) {
            if (!((bm >> (w*4 + r)) & 1u)) {
                float acc = v[r][0].x*q0.x + v[r][0].y*q0.y + v[r][0].z*q0.z + v[r][0].w*q0.w
                          + v[r][1].x*q1.x + v[r][1].y*q1.y + v[r][1].z*q1.z + v[r][1].w*q1.w;
                acc = warp_sum(acc);
                if (lane == 0) s_val[w*4 + r] = acc;
            } else if (lane == 0) {
                s_val[w*4 + r] = -INFINITY;
            }
        }
        __syncthreads();
        if (w == 0) {
            float vv = s_val[lane];
            float mx = warp_max(vv);
            float au;
            if (mx == -INFINITY) {
                au = 0.f;                       // all-masked entity
            } else {
                float ex = (vv == -INFINITY) ? 0.f : __expf(vv - mx);
                float sm = warp_sum(ex);
                au = ex / sm;
            }
            out[OUT_AU + b * S_ + e * ENT_ + lane] = au;
        }
    } else {
        int b = blockIdx.x - 2048;
        __shared__ __align__(16) float sqc[D_];
        __shared__ float s_sc[C_];
        {
            float4 q = make_float4(0.f, 0.f, 0.f, 0.f);
            #pragma unroll
            for (int ks = 0; ks < KSPL; ks++) {
                float4 p = ((const float4*)g_qp[ks])[b * ((UD_+D_)/4) + 64 + t];
                q.x += p.x; q.y += p.y; q.z += p.z; q.w += p.w;
            }
            ((float4*)sqc)[t] = q;
        }
        __syncthreads();
        int mhl = g_mode_hl;
        for (int c = w; c < C_; c += 8) {
            if (read_mask(hlm, b * C_ + c, mhl)) {
                if (lane == 0) s_sc[c] = -INFINITY;
                continue;
            }
            const float4* p = (const float4*)hl + ((size_t)c * B_ + b) * (D_/4);
            float acc = 0.f;
            #pragma unroll
            for (int it = 0; it < 8; it++) {
                float4 x = p[lane + it*32];
                float4 y = ((const float4*)sqc)[lane + it*32];
                acc += x.x*y.x + x.y*y.y + x.z*y.z + x.w*y.w;
            }
            acc = warp_sum(acc);
            if (lane == 0) s_sc[c] = acc;
        }
        __syncthreads();
        if (t == 0) {
            float mx = -INFINITY;
            for (int c = 0; c < C_; c++) mx = fmaxf(mx, s_sc[c]);
            float sum = 0.f;
            for (int c = 0; c < C_; c++) {
                float e = (s_sc[c] == -INFINITY) ? 0.f : __expf(s_sc[c] - mx);
                s_sc[c] = e; sum += e;
            }
            float inv = 1.f / sum;
            for (int c = 1; c < C_; c++) {
                float vv = s_sc[c] * inv;
                g_acs[b * NENT_ + (c-1)] = vv;
                out[OUT_AC + b * (C_-1) + (c-1)] = vv;
            }
        }
    }
}

// ---------------------------------------------------------------------------
// K3 context. Block = (entity e, batch b, D-half); computes av = au*ac[e]
// (writes av output), ballot-compacts nonzero weights, up to 16 LDG.128 in
// flight before FMAs (mean cnt ~= 16 -> usually one swoop), RED.ADD.F32
// into g_c. ~75% of rows exactly zero -> never loaded.
// ---------------------------------------------------------------------------
__global__ void k_context(const float* __restrict__ ll, float* __restrict__ out) {
    int e = blockIdx.x, b = blockIdx.y, half = blockIdx.z, t = threadIdx.x;
    __shared__ float sw[ENT_];
    __shared__ int   sidx[ENT_];
    __shared__ int   scnt;
    float ac = g_acs[b * NENT_ + e];
    if (t < 32) {
        float au = out[OUT_AU + b * S_ + e * ENT_ + t];
        float av = au * ac;
        if (half == 0) out[OUT_AV + b * S_ + e * ENT_ + t] = av;
        unsigned m = __ballot_sync(0xFFFFFFFFu, av != 0.f);
        int pos = __popc(m & ((1u << t) - 1u));
        if (av != 0.f) { sw[pos] = av; sidx[pos] = t; }
        if (t == 0) scnt = __popc(m);
    }
    __syncthreads();
    int cnt = scnt;
    if (cnt == 0) return;
    float4 acc = make_float4(0.f, 0.f, 0.f, 0.f);
    const float4* base = (const float4*)ll + (size_t)b * (D_/4) + half * 128 + t;
    const size_t RS = (size_t)B_ * D_ / 4;
    int k = 0;
    for (; k + 16 <= cnt; k += 16) {
        float4 v[16];
        #pragma unroll
        for (int u = 0; u < 16; u++)
            v[u] = base[(size_t)(e * ENT_ + sidx[k + u]) * RS];
        #pragma unroll
        for (int u = 0; u < 16; u++) {
            float w = sw[k + u];
            acc.x += w * v[u].x; acc.y += w * v[u].y;
            acc.z += w * v[u].z; acc.w += w * v[u].w;
        }
    }
    for (; k + 8 <= cnt; k += 8) {
        float4 v[8];
        #pragma unroll
        for (int u = 0; u < 8; u++)
            v[u] = base[(size_t)(e * ENT_ + sidx[k + u]) * RS];
        #pragma unroll
        for (int u = 0; u < 8; u++) {
            float w = sw[k + u];
            acc.x += w * v[u].x; acc.y += w * v[u].y;
            acc.z += w * v[u].z; acc.w += w * v[u].w;
        }
    }
    for (; k + 4 <= cnt; k += 4) {
        float4 v[4];
        #pragma unroll
        for (int u = 0; u < 4; u++)
            v[u] = base[(size_t)(e * ENT_ + sidx[k + u]) * RS];
        #pragma unroll
        for (int u = 0; u < 4; u++) {
            float w = sw[k + u];
            acc.x += w * v[u].x; acc.y += w * v[u].y;
            acc.z += w * v[u].z; acc.w += w * v[u].w;
        }
    }
    for (; k < cnt; k++) {
        float4 v = base[(size_t)(e * ENT_ + sidx[k]) * RS];
        float w = sw[k];
        acc.x += w * v.x; acc.y += w * v.y; acc.z += w * v.z; acc.w += w * v.w;
    }
    float* dst = &g_c[b * D_ + half * 512 + t * 4];
    atomicAdd(dst + 0, acc.x);
    atomicAdd(dst + 1, acc.y);
    atomicAdd(dst + 2, acc.z);
    atomicAdd(dst + 3, acc.w);
}

// ---------------------------------------------------------------------------
// K4: c-half of the output GEMM: g_hc[ks] = g_c @ Wo[:, :1024]^T partials.
// 32 n-groups x 4 K-splits = 128 blocks.
// ---------------------------------------------------------------------------
__global__ void k_gemm_c(const float* __restrict__ Wo) {
    int g = blockIdx.x >> 2, ks = blockIdx.x & 3;
    int n0 = g * 32;
    gemm_tile(g_c, D_, Wo + (size_t)n0 * (2*D_), 2*D_,
              ks * 256, 4, &g_hc[ks][n0], D_);
}

// ---------------------------------------------------------------------------
// K5: attn_h = tanh(sum of all 8 partials).
// ---------------------------------------------------------------------------
__global__ void k_tanh(float* __restrict__ out) {
    int i = blockIdx.x * 256 + threadIdx.x;   // float4 index, 8192 total
    float4 s = make_float4(0.f, 0.f, 0.f, 0.f);
    #pragma unroll
    for (int ks = 0; ks < KSPL; ks++) {
        float4 a = ((const float4*)g_hc[ks])[i];
        float4 b = ((const float4*)g_hs[ks])[i];
        s.x += a.x + b.x; s.y += a.y + b.y;
        s.z += a.z + b.z; s.w += a.w + b.w;
    }
    float4 r;
    r.x = tanhf(s.x); r.y = tanhf(s.y); r.z = tanhf(s.z); r.w = tanhf(s.w);
    ((float4*)(out + OUT_ATTN))[i] = r;
}

// ---------------------------------------------------------------------------
extern "C" void kernel_launch(void* const* d_in, const int* in_sizes, int n_in,
                              void* d_out, int out_size) {
    const float* src = (const float*)d_in[0];
    const float* hl  = (const float*)d_in[1];
    const float* pe  = (const float*)d_in[2];
    const float* ll  = (const float*)d_in[3];
    const void*  llm = d_in[4];
    const void*  hlm = d_in[5];
    const float* Wu  = (const float*)d_in[6];
    const float* Wc  = (const float*)d_in[7];
    const float* Wo  = (const float*)d_in[8];
    float* out = (float*)d_out;

    k_front<<<290, 128>>>(src, Wu, Wc, Wo,
                          (const unsigned int*)llm, (const unsigned int*)hlm);
    k_align<<<2048 + 32, 256>>>(pe, hl, llm, hlm, out);
    k_context<<<dim3(NENT_, B_, 2), 128>>>(ll, out);
    k_gemm_c<<<128, 128>>>(Wo);
    k_tanh<<<32, 256>>>(out);
}

// round 13
// speedup vs baseline: 1.6438x; 1.0055x over previous
#include <cuda_runtime.h>
#include <math.h>

// HierarchicalAttention — GB300 sm_103a, R12
// 5 launches: front(proj + src-half GEMM, K-split partials, detect)
//          -> align(dots + both softmaxes + zero g_c)
//          -> context(sparse weighted sum, atomics into g_c)
//          -> gemm_c(c-half GEMM, K-split partials)
//          -> tanh(sum partials + tanh)
//
// Output: attn_h (B,D) | align_vectors (B,S) | ac (B,C-1) | au (B,S)

#define B_    32
#define D_    1024
#define UD_   256
#define ENT_  32
#define NENT_ 64
#define S_    2048
#define C_    65
#define KSPL  4

#define OUT_ATTN 0
#define OUT_AV   (B_*D_)
#define OUT_AC   (OUT_AV + B_*S_)
#define OUT_AU   (OUT_AC + B_*(C_-1))

// ---- static scratch ----
__device__ float g_qp[KSPL][B_*(UD_+D_)];  // proj partials: [m*1280 + n] (n<256 qu, else qc)
__device__ float g_hs[KSPL][B_*D_];        // src-half of output GEMM, partials
__device__ float g_hc[KSPL][B_*D_];        // c-half of output GEMM, partials
__device__ float g_acs[B_*NENT_];          // chunk softmax (chunks 1..64)
__device__ float g_c[B_*D_];               // atomically accumulated context
__device__ int   g_mode_ll;                // 0=int32, 1=float32, 2=uint8
__device__ int   g_mode_hl;

__device__ __forceinline__ bool read_mask(const void* p, int idx, int mode) {
    if (mode == 0) return ((const int*)p)[idx] != 0;
    if (mode == 1) return ((const float*)p)[idx] != 0.0f;
    return ((const unsigned char*)p)[idx] != 0;
}
__device__ __forceinline__ float warp_sum(float v) {
    #pragma unroll
    for (int o = 16; o; o >>= 1) v += __shfl_xor_sync(0xFFFFFFFFu, v, o);
    return v;
}
__device__ __forceinline__ float warp_max(float v) {
    #pragma unroll
    for (int o = 16; o; o >>= 1) v = fmaxf(v, __shfl_xor_sync(0xFFFFFFFFu, v, o));
    return v;
}

// ---------------------------------------------------------------------------
// GEMM primitive: 32(M)x32(N) output tile over `ntiles` K-tiles of 64.
// 128 threads: lane = m (M == warpsize), warp owns 8 n-columns.
// Inner chunk: 1 As LDS.128 + 8 broadcast Bs LDS.128 + 32 FFMA
//   -> As crossbar bytes amortized over 8 outputs (vs 1 before: the 8x
//      redundancy that made R11's GEMMs L1-bound at occ 12% is gone).
// dst[m*ldd + n] (plain stores to a per-K-split partial buffer; no atomics).
// ---------------------------------------------------------------------------
__device__ __forceinline__ void gemm_tile(const float* __restrict__ A, int lda,
                                          const float* __restrict__ Bn, int ldb,
                                          int k0, int ntiles,
                                          float* __restrict__ dst, int ldd) {
    __shared__ __align__(16) float As[32][68];
    __shared__ __align__(16) float Bs[32][68];
    int t = threadIdx.x, lane = t & 31, wid = t >> 5;
    float acc[8];
    #pragma unroll
    for (int j = 0; j < 8; j++) acc[j] = 0.f;

    for (int kt = 0; kt < ntiles; kt++) {
        int kk0 = k0 + kt * 64;
        #pragma unroll
        for (int i = 0; i < 4; i++) {
            int idx = t + i * 128;              // 512 float4 each
            int r = idx >> 4, c = (idx & 15) * 4;
            *(float4*)&As[r][c] = *(const float4*)&A [(size_t)r * lda + kk0 + c];
            *(float4*)&Bs[r][c] = *(const float4*)&Bn[(size_t)r * ldb + kk0 + c];
        }
        __syncthreads();
        #pragma unroll
        for (int i = 0; i < 16; i++) {
            float4 a = *(const float4*)&As[lane][i * 4];
            #pragma unroll
            for (int j = 0; j < 8; j++) {
                float4 b = *(const float4*)&Bs[wid * 8 + j][i * 4];
                acc[j] += a.x*b.x + a.y*b.y + a.z*b.z + a.w*b.w;
            }
        }
        __syncthreads();
    }
    #pragma unroll
    for (int j = 0; j < 8; j++)
        dst[lane * ldd + wid * 8 + j] = acc[j];
}

// ---------------------------------------------------------------------------
// K1 front:
//  [0,160):   proj GEMM  (40 n-groups x 4 K-splits) -> g_qp[ks]
//  [160,288): src-half of output GEMM (32 n-groups x 4 K-splits) -> g_hs[ks]
//  [288,290): mask dtype detection
// ---------------------------------------------------------------------------
__global__ void k_front(const float* __restrict__ src,
                        const float* __restrict__ Wu,
                        const float* __restrict__ Wc,
                        const float* __restrict__ Wo,
                        const unsigned int* __restrict__ llm,
                        const unsigned int* __restrict__ hlm) {
    int bx = blockIdx.x, t = threadIdx.x;
    if (bx >= 288) {
        // int32 words are {0,1}; f32 words are {0,0x3F800000}; packed uint8
        // words hit neither set (random 0/1 data).
        __shared__ int s_ni, s_nf;
        if (t == 0) { s_ni = 0; s_nf = 0; }
        __syncthreads();
        int which = bx - 288;
        const unsigned int* p = which ? hlm : llm;
        int n = which ? (B_*C_ / 4) : (NENT_*B_*ENT_ / 4);
        int ni = 0, nf = 0;
        for (int i = t; i < n; i += blockDim.x) {
            unsigned int w = p[i];
            if (w > 1u) ni = 1;
            if (w != 0u && w != 0x3F800000u) nf = 1;
        }
        if (ni) atomicOr(&s_ni, 1);
        if (nf) atomicOr(&s_nf, 1);
        __syncthreads();
        if (t == 0) {
            int mode = (!s_ni) ? 0 : ((!s_nf) ? 1 : 2);
            if (which) g_mode_hl = mode; else g_mode_ll = mode;
        }
        return;
    }
    if (bx < 160) {
        int g = bx >> 2, ks = bx & 3;
        int n0 = g * 32;
        const float* Bn;
        if (n0 < 256) Bn = Wu + (size_t)n0 * D_;
        else          Bn = Wc + (size_t)(n0 - 256) * D_;
        gemm_tile(src, D_, Bn, D_, ks * 256, 4, &g_qp[ks][n0], UD_ + D_);
    } else {
        int h = bx - 160;
        int g = h >> 2, ks = h & 3;
        int n0 = g * 32;
        gemm_tile(src, D_, Wo + (size_t)n0 * (2*D_) + D_, 2*D_,
                  ks * 256, 4, &g_hs[ks][n0], D_);
    }
}

// ---------------------------------------------------------------------------
// K2 align — alignment dots + both softmaxes; first 256 unit blocks also
// zero g_c for K3's atomics.
//  [0,2048): unit blocks (e,b): q_u (= sum of proj partials) staged in smem,
//            masked rows skipped (zero traffic), batched LDG.128, block-local
//            per-entity masked softmax; writes au to out.
//  [2048,2080): chunk blocks (one per b): 65 chunk dots + softmax; writes ac.
// ---------------------------------------------------------------------------
__global__ void k_align(const float* __restrict__ pe,
                        const float* __restrict__ hl,
                        const void* llm, const void* hlm,
                        float* __restrict__ out) {
    int t = threadIdx.x, w = t >> 5, lane = t & 31;
    if (blockIdx.x < 2048) {
        int b = blockIdx.x & 31, e = blockIdx.x >> 5;
        if (blockIdx.x < 256 && t < 32)
            ((float4*)g_c)[blockIdx.x * 32 + t] = make_float4(0.f, 0.f, 0.f, 0.f);
        __shared__ __align__(16) float sq[UD_];
        __shared__ float s_val[ENT_];
        __shared__ unsigned s_bm;
        if (t < 64) {
            float4 q = make_float4(0.f, 0.f, 0.f, 0.f);
            #pragma unroll
            for (int ks = 0; ks < KSPL; ks++) {
                float4 p = ((const float4*)g_qp[ks])[b * ((UD_+D_)/4) + t];
                q.x += p.x; q.y += p.y; q.z += p.z; q.w += p.w;
            }
            ((float4*)sq)[t] = q;
        }
        if (w == 0) {
            bool mk = read_mask(llm, e * (B_*ENT_) + b * ENT_ + lane, g_mode_ll);
            unsigned bm = __ballot_sync(0xFFFFFFFFu, mk);
            if (lane == 0) s_bm = bm;
        }
        __syncthreads();
        unsigned bm = s_bm;
        float4 q0 = ((const float4*)sq)[lane];
        float4 q1 = ((const float4*)sq)[lane + 32];
        const float4* peb = (const float4*)pe + (size_t)b * (UD_/4) + lane;
        const size_t RS = (size_t)B_ * UD_ / 4;
        int s0 = e * ENT_ + w * 4;
        float4 v[4][2];
        #pragma unroll
        for (int r = 0; r < 4; r++) {
            if (!((bm >> (w*4 + r)) & 1u)) {
                const float4* p = peb + (size_t)(s0 + r) * RS;
                v[r][0] = p[0];
                v[r][1] = p[32];
            }
        }
        #pragma unroll
        for (int r = 0; r < 4; r++) {
            if (!((bm >> (w*4 + r)) & 1u)) {
                float acc = v[r][0].x*q0.x + v[r][0].y*q0.y + v[r][0].z*q0.z + v[r][0].w*q0.w
                          + v[r][1].x*q1.x + v[r][1].y*q1.y + v[r][1].z*q1.z + v[r][1].w*q1.w;
                acc = warp_sum(acc);
                if (lane == 0) s_val[w*4 + r] = acc;
            } else if (lane == 0) {
                s_val[w*4 + r] = -INFINITY;
            }
        }
        __syncthreads();
        if (w == 0) {
            float vv = s_val[lane];
            float mx = warp_max(vv);
            float au;
            if (mx == -INFINITY) {
                au = 0.f;                       // all-masked entity
            } else {
                float ex = (vv == -INFINITY) ? 0.f : __expf(vv - mx);
                float sm = warp_sum(ex);
                au = ex / sm;
            }
            out[OUT_AU + b * S_ + e * ENT_ + lane] = au;
        }
    } else {
        int b = blockIdx.x - 2048;
        __shared__ __align__(16) float sqc[D_];
        __shared__ float s_sc[C_];
        {
            float4 q = make_float4(0.f, 0.f, 0.f, 0.f);
            #pragma unroll
            for (int ks = 0; ks < KSPL; ks++) {
                float4 p = ((const float4*)g_qp[ks])[b * ((UD_+D_)/4) + 64 + t];
                q.x += p.x; q.y += p.y; q.z += p.z; q.w += p.w;
            }
            ((float4*)sqc)[t] = q;
        }
        __syncthreads();
        int mhl = g_mode_hl;
        for (int c = w; c < C_; c += 8) {
            if (read_mask(hlm, b * C_ + c, mhl)) {
                if (lane == 0) s_sc[c] = -INFINITY;
                continue;
            }
            const float4* p = (const float4*)hl + ((size_t)c * B_ + b) * (D_/4);
            float acc = 0.f;
            #pragma unroll
            for (int it = 0; it < 8; it++) {
                float4 x = p[lane + it*32];
                float4 y = ((const float4*)sqc)[lane + it*32];
                acc += x.x*y.x + x.y*y.y + x.z*y.z + x.w*y.w;
            }
            acc = warp_sum(acc);
            if (lane == 0) s_sc[c] = acc;
        }
        __syncthreads();
        if (t == 0) {
            float mx = -INFINITY;
            for (int c = 0; c < C_; c++) mx = fmaxf(mx, s_sc[c]);
            float sum = 0.f;
            for (int c = 0; c < C_; c++) {
                float e = (s_sc[c] == -INFINITY) ? 0.f : __expf(s_sc[c] - mx);
                s_sc[c] = e; sum += e;
            }
            float inv = 1.f / sum;
            for (int c = 1; c < C_; c++) {
                float vv = s_sc[c] * inv;
                g_acs[b * NENT_ + (c-1)] = vv;
                out[OUT_AC + b * (C_-1) + (c-1)] = vv;
            }
        }
    }
}

// ---------------------------------------------------------------------------
// K3 context. Block = (entity e, batch b, D-half); computes av = au*ac[e]
// (writes av output), ballot-compacts nonzero weights, up to 16 LDG.128 in
// flight before FMAs (mean cnt ~= 16 -> usually one swoop), RED.ADD.F32
// into g_c. ~75% of rows exactly zero -> never loaded.
// ---------------------------------------------------------------------------
__global__ void k_context(const float* __restrict__ ll, float* __restrict__ out) {
    int e = blockIdx.x, b = blockIdx.y, half = blockIdx.z, t = threadIdx.x;
    __shared__ float sw[ENT_];
    __shared__ int   sidx[ENT_];
    __shared__ int   scnt;
    float ac = g_acs[b * NENT_ + e];
    if (t < 32) {
        float au = out[OUT_AU + b * S_ + e * ENT_ + t];
        float av = au * ac;
        if (half == 0) out[OUT_AV + b * S_ + e * ENT_ + t] = av;
        unsigned m = __ballot_sync(0xFFFFFFFFu, av != 0.f);
        int pos = __popc(m & ((1u << t) - 1u));
        if (av != 0.f) { sw[pos] = av; sidx[pos] = t; }
        if (t == 0) scnt = __popc(m);
    }
    __syncthreads();
    int cnt = scnt;
    if (cnt == 0) return;
    float4 acc = make_float4(0.f, 0.f, 0.f, 0.f);
    const float4* base = (const float4*)ll + (size_t)b * (D_/4) + half * 128 + t;
    const size_t RS = (size_t)B_ * D_ / 4;
    int k = 0;
    for (; k + 16 <= cnt; k += 16) {
        float4 v[16];
        #pragma unroll
        for (int u = 0; u < 16; u++)
            v[u] = base[(size_t)(e * ENT_ + sidx[k + u]) * RS];
        #pragma unroll
        for (int u = 0; u < 16; u++) {
            float w = sw[k + u];
            acc.x += w * v[u].x; acc.y += w * v[u].y;
            acc.z += w * v[u].z; acc.w += w * v[u].w;
        }
    }
    for (; k + 8 <= cnt; k += 8) {
        float4 v[8];
        #pragma unroll
        for (int u = 0; u < 8; u++)
            v[u] = base[(size_t)(e * ENT_ + sidx[k + u]) * RS];
        #pragma unroll
        for (int u = 0; u < 8; u++) {
            float w = sw[k + u];
            acc.x += w * v[u].x; acc.y += w * v[u].y;
            acc.z += w * v[u].z; acc.w += w * v[u].w;
        }
    }
    for (; k + 4 <= cnt; k += 4) {
        float4 v[4];
        #pragma unroll
        for (int u = 0; u < 4; u++)
            v[u] = base[(size_t)(e * ENT_ + sidx[k + u]) * RS];
        #pragma unroll
        for (int u = 0; u < 4; u++) {
            float w = sw[k + u];
            acc.x += w * v[u].x; acc.y += w * v[u].y;
            acc.z += w * v[u].z; acc.w += w * v[u].w;
        }
    }
    for (; k < cnt; k++) {
        float4 v = base[(size_t)(e * ENT_ + sidx[k]) * RS];
        float w = sw[k];
        acc.x += w * v.x; acc.y += w * v.y; acc.z += w * v.z; acc.w += w * v.w;
    }
    float* dst = &g_c[b * D_ + half * 512 + t * 4];
    atomicAdd(dst + 0, acc.x);
    atomicAdd(dst + 1, acc.y);
    atomicAdd(dst + 2, acc.z);
    atomicAdd(dst + 3, acc.w);
}

// ---------------------------------------------------------------------------
// K4: c-half of the output GEMM: g_hc[ks] = g_c @ Wo[:, :1024]^T partials.
// 32 n-groups x 4 K-splits = 128 blocks.
// ---------------------------------------------------------------------------
__global__ void k_gemm_c(const float* __restrict__ Wo) {
    int g = blockIdx.x >> 2, ks = blockIdx.x & 3;
    int n0 = g * 32;
    gemm_tile(g_c, D_, Wo + (size_t)n0 * (2*D_), 2*D_,
              ks * 256, 4, &g_hc[ks][n0], D_);
}

// ---------------------------------------------------------------------------
// K5: attn_h = tanh(sum of all 8 partials).
// ---------------------------------------------------------------------------
__global__ void k_tanh(float* __restrict__ out) {
    int i = blockIdx.x * 256 + threadIdx.x;   // float4 index, 8192 total
    float4 s = make_float4(0.f, 0.f, 0.f, 0.f);
    #pragma unroll
    for (int ks = 0; ks < KSPL; ks++) {
        float4 a = ((const float4*)g_hc[ks])[i];
        float4 b = ((const float4*)g_hs[ks])[i];
        s.x += a.x + b.x; s.y += a.y + b.y;
        s.z += a.z + b.z; s.w += a.w + b.w;
    }
    float4 r;
    r.x = tanhf(s.x); r.y = tanhf(s.y); r.z = tanhf(s.z); r.w = tanhf(s.w);
    ((float4*)(out + OUT_ATTN))[i] = r;
}

// ---------------------------------------------------------------------------
extern "C" void kernel_launch(void* const* d_in, const int* in_sizes, int n_in,
                              void* d_out, int out_size) {
    const float* src = (const float*)d_in[0];
    const float* hl  = (const float*)d_in[1];
    const float* pe  = (const float*)d_in[2];
    const float* ll  = (const float*)d_in[3];
    const void*  llm = d_in[4];
    const void*  hlm = d_in[5];
    const float* Wu  = (const float*)d_in[6];
    const float* Wc  = (const float*)d_in[7];
    const float* Wo  = (const float*)d_in[8];
    float* out = (float*)d_out;

    k_front<<<290, 128>>>(src, Wu, Wc, Wo,
                          (const unsigned int*)llm, (const unsigned int*)hlm);
    k_align<<<2048 + 32, 256>>>(pe, hl, llm, hlm, out);
    k_context<<<dim3(NENT_, B_, 2), 128>>>(ll, out);
    k_gemm_c<<<128, 128>>>(Wo);
    k_tanh<<<32, 256>>>(out);
}